// round 1
// baseline (speedup 1.0000x reference)
#include <cuda_runtime.h>
#include <cstdint>

// Problem constants (from reference)
#define H 16
#define D 64
#define S 1024
#define START_FRAME 9728
#define NKV 8192        // attention window length
#define CACHE_OFF 2560  // window j -> cache index 2560+j  (for j < SPLIT)
#define SPLIT 7168      // j >= SPLIT -> new tokens (j - SPLIT)
#define BM 64
#define BN 64
#define KSTRIDE 68      // 68 % 32 == 4  -> conflict-free K B-frag / P A-frag loads
#define VSTRIDE 72      // 72 % 32 == 8  -> conflict-free V B-frag loads

// Scratch (allocation-free rule: __device__ globals)
__device__ float g_qr[S * H * D];
__device__ float g_kr[S * H * D];

// ---------------------------------------------------------------------------
// RoPE prep: q_rope, k_rope into scratch. One thread per (s, h, pair).
// ---------------------------------------------------------------------------
__global__ void rope_prep(const float* __restrict__ q, const float* __restrict__ k,
                          const float* __restrict__ fc, const float* __restrict__ fs) {
    int idx = blockIdx.x * blockDim.x + threadIdx.x;  // S*H*32 pairs
    if (idx >= S * H * 32) return;
    int p = idx & 31;
    int h = (idx >> 5) & 15;
    int s = idx >> 9;
    int pos = START_FRAME + s;
    float c  = fc[pos * 64 + 2 * p];
    float sn = fs[pos * 64 + 2 * p];
    int base = (s * H + h) * D + 2 * p;
    float q1 = q[base], q2 = q[base + 1];
    g_qr[base]     = q1 * c - q2 * sn;
    g_qr[base + 1] = q2 * c + q1 * sn;
    float k1 = k[base], k2 = k[base + 1];
    g_kr[base]     = k1 * c - k2 * sn;
    g_kr[base + 1] = k2 * c + k1 * sn;
}

// ---------------------------------------------------------------------------
// Helpers
// ---------------------------------------------------------------------------
__device__ __forceinline__ uint32_t f2tf(float f) {
    uint32_t r;
    asm("cvt.rna.tf32.f32 %0, %1;" : "=r"(r) : "f"(f));
    return r;
}
__device__ __forceinline__ float f2tf_f(float f) { return __uint_as_float(f2tf(f)); }

__device__ __forceinline__ float ex2(float x) {
    float y;
    asm("ex2.approx.f32 %0, %1;" : "=f"(y) : "f"(x));
    return y;
}

__device__ __forceinline__ void mma_tf32(float* c,
                                         uint32_t a0, uint32_t a1, uint32_t a2, uint32_t a3,
                                         uint32_t b0, uint32_t b1) {
    asm volatile(
        "mma.sync.aligned.m16n8k8.row.col.f32.tf32.tf32.f32 "
        "{%0,%1,%2,%3}, {%4,%5,%6,%7}, {%8,%9}, {%0,%1,%2,%3};\n"
        : "+f"(c[0]), "+f"(c[1]), "+f"(c[2]), "+f"(c[3])
        : "r"(a0), "r"(a1), "r"(a2), "r"(a3), "r"(b0), "r"(b1));
}

// ---------------------------------------------------------------------------
// Flash attention, tf32 mma.sync. grid = (S/BM, H), block = 128 (4 warps).
// smem: K tile [64][68], V tile [64][72], P/Q-stage tile [64][68]
// ---------------------------------------------------------------------------
__global__ __launch_bounds__(128) void attn_kernel(
    const float* __restrict__ v_in,
    const float* __restrict__ cache_k,
    const float* __restrict__ cache_v,
    float* __restrict__ out)
{
    extern __shared__ float smem[];
    float* ksm = smem;                      // BN * KSTRIDE
    float* vsm = ksm + BN * KSTRIDE;        // BN * VSTRIDE
    float* psm = vsm + BN * VSTRIDE;        // BM * KSTRIDE

    const int h    = blockIdx.y;
    const int q0   = blockIdx.x * BM;
    const int tid  = threadIdx.x;
    const int warp = tid >> 5;
    const int lane = tid & 31;
    const int gid  = lane >> 2;   // groupID (row within fragment)
    const int tig  = lane & 3;    // threadID_in_group (col within fragment)

    // scale * log2(e) folded into Q -> scores live in log2 domain
    const float SCALE_LOG2E = 1.4426950408889634f * 0.125f;

    // ---- stage Q tile into psm, build per-warp tf32 A-fragments ----
    for (int i = tid; i < BM * 16; i += 128) {  // float4 granules
        int r = i >> 4, c4 = (i & 15) << 2;
        float4 qv = *(const float4*)&g_qr[((q0 + r) * H + h) * D + c4];
        *(float4*)&psm[r * KSTRIDE + c4] = qv;
    }
    __syncthreads();

    uint32_t qa[8][4];
    {
        int r0 = warp * 16 + gid;
        #pragma unroll
        for (int kk = 0; kk < 8; kk++) {
            int c0 = kk * 8 + tig;
            qa[kk][0] = f2tf(psm[r0 * KSTRIDE + c0] * SCALE_LOG2E);
            qa[kk][1] = f2tf(psm[(r0 + 8) * KSTRIDE + c0] * SCALE_LOG2E);
            qa[kk][2] = f2tf(psm[r0 * KSTRIDE + c0 + 4] * SCALE_LOG2E);
            qa[kk][3] = f2tf(psm[(r0 + 8) * KSTRIDE + c0 + 4] * SCALE_LOG2E);
        }
    }

    float o[8][4];
    #pragma unroll
    for (int i = 0; i < 8; i++) { o[i][0] = 0.f; o[i][1] = 0.f; o[i][2] = 0.f; o[i][3] = 0.f; }
    float M0 = -1e30f, M1 = -1e30f, L0 = 0.f, L1 = 0.f;

    for (int jt = 0; jt < NKV / BN; jt++) {
        // source select: rolled cache vs. freshly roped K / raw V (tile-aligned split)
        const float* kp; const float* vp; int rowbase;
        if (jt < SPLIT / BN) { kp = cache_k; vp = cache_v; rowbase = CACHE_OFF + jt * BN; }
        else                 { kp = g_kr;    vp = v_in;    rowbase = jt * BN - SPLIT; }

        // ---- load K,V tiles (tf32-rounded at the copy) ----
        for (int i = tid; i < BN * 16; i += 128) {
            int r = i >> 4, c4 = (i & 15) << 2;
            int goff = ((rowbase + r) * H + h) * D + c4;
            float4 kv = *(const float4*)&kp[goff];
            *(float4*)&ksm[r * KSTRIDE + c4] =
                make_float4(f2tf_f(kv.x), f2tf_f(kv.y), f2tf_f(kv.z), f2tf_f(kv.w));
            float4 vv = *(const float4*)&vp[goff];
            *(float4*)&vsm[r * VSTRIDE + c4] =
                make_float4(f2tf_f(vv.x), f2tf_f(vv.y), f2tf_f(vv.z), f2tf_f(vv.w));
        }
        __syncthreads();

        // ---- S = Q * K^T (in log2 domain) ----
        float sacc[8][4];
        #pragma unroll
        for (int i = 0; i < 8; i++) { sacc[i][0] = 0.f; sacc[i][1] = 0.f; sacc[i][2] = 0.f; sacc[i][3] = 0.f; }
        #pragma unroll
        for (int kk = 0; kk < 8; kk++) {
            #pragma unroll
            for (int nn = 0; nn < 8; nn++) {
                uint32_t b0 = __float_as_uint(ksm[(nn * 8 + gid) * KSTRIDE + kk * 8 + tig]);
                uint32_t b1 = __float_as_uint(ksm[(nn * 8 + gid) * KSTRIDE + kk * 8 + tig + 4]);
                mma_tf32(sacc[nn], qa[kk][0], qa[kk][1], qa[kk][2], qa[kk][3], b0, b1);
            }
        }

        // ---- online softmax (base-2) ----
        float mx0 = -1e30f, mx1 = -1e30f;
        #pragma unroll
        for (int nn = 0; nn < 8; nn++) {
            mx0 = fmaxf(mx0, fmaxf(sacc[nn][0], sacc[nn][1]));
            mx1 = fmaxf(mx1, fmaxf(sacc[nn][2], sacc[nn][3]));
        }
        mx0 = fmaxf(mx0, __shfl_xor_sync(0xffffffffu, mx0, 1));
        mx0 = fmaxf(mx0, __shfl_xor_sync(0xffffffffu, mx0, 2));
        mx1 = fmaxf(mx1, __shfl_xor_sync(0xffffffffu, mx1, 1));
        mx1 = fmaxf(mx1, __shfl_xor_sync(0xffffffffu, mx1, 2));
        float nm0 = fmaxf(M0, mx0), nm1 = fmaxf(M1, mx1);
        float sc0 = ex2(M0 - nm0), sc1 = ex2(M1 - nm1);
        M0 = nm0; M1 = nm1;

        float ls0 = 0.f, ls1 = 0.f;
        {
            int r0 = warp * 16 + gid;
            #pragma unroll
            for (int nn = 0; nn < 8; nn++) {
                float p0 = ex2(sacc[nn][0] - M0);
                float p1 = ex2(sacc[nn][1] - M0);
                float p2 = ex2(sacc[nn][2] - M1);
                float p3 = ex2(sacc[nn][3] - M1);
                ls0 += p0 + p1;
                ls1 += p2 + p3;
                int cb = nn * 8 + 2 * tig;
                psm[r0 * KSTRIDE + cb]           = f2tf_f(p0);
                psm[r0 * KSTRIDE + cb + 1]       = f2tf_f(p1);
                psm[(r0 + 8) * KSTRIDE + cb]     = f2tf_f(p2);
                psm[(r0 + 8) * KSTRIDE + cb + 1] = f2tf_f(p3);
            }
        }
        ls0 += __shfl_xor_sync(0xffffffffu, ls0, 1);
        ls0 += __shfl_xor_sync(0xffffffffu, ls0, 2);
        ls1 += __shfl_xor_sync(0xffffffffu, ls1, 1);
        ls1 += __shfl_xor_sync(0xffffffffu, ls1, 2);
        L0 = L0 * sc0 + ls0;
        L1 = L1 * sc1 + ls1;
        #pragma unroll
        for (int nn = 0; nn < 8; nn++) {
            o[nn][0] *= sc0; o[nn][1] *= sc0; o[nn][2] *= sc1; o[nn][3] *= sc1;
        }

        __syncwarp();  // P: own-row cross-lane visibility within warp

        // ---- O += P * V ----
        {
            int r0 = warp * 16 + gid;
            #pragma unroll
            for (int kk = 0; kk < 8; kk++) {
                uint32_t a0 = __float_as_uint(psm[r0 * KSTRIDE + kk * 8 + tig]);
                uint32_t a1 = __float_as_uint(psm[(r0 + 8) * KSTRIDE + kk * 8 + tig]);
                uint32_t a2 = __float_as_uint(psm[r0 * KSTRIDE + kk * 8 + tig + 4]);
                uint32_t a3 = __float_as_uint(psm[(r0 + 8) * KSTRIDE + kk * 8 + tig + 4]);
                #pragma unroll
                for (int nn = 0; nn < 8; nn++) {
                    uint32_t b0 = __float_as_uint(vsm[(kk * 8 + tig) * VSTRIDE + nn * 8 + gid]);
                    uint32_t b1 = __float_as_uint(vsm[(kk * 8 + tig + 4) * VSTRIDE + nn * 8 + gid]);
                    mma_tf32(o[nn], a0, a1, a2, a3, b0, b1);
                }
            }
        }
        __syncthreads();  // before next tile overwrites ksm/vsm (and psm reads done)
    }

    // ---- normalize + write out[s, h*64 + d] ----
    float inv0 = 1.f / L0, inv1 = 1.f / L1;
    int r0 = q0 + warp * 16 + gid;
    #pragma unroll
    for (int nn = 0; nn < 8; nn++) {
        int cb = h * 64 + nn * 8 + 2 * tig;
        float2 w0 = make_float2(o[nn][0] * inv0, o[nn][1] * inv0);
        float2 w1 = make_float2(o[nn][2] * inv1, o[nn][3] * inv1);
        *(float2*)&out[r0 * (H * D) + cb]       = w0;
        *(float2*)&out[(r0 + 8) * (H * D) + cb] = w1;
    }
}

// ---------------------------------------------------------------------------
extern "C" void kernel_launch(void* const* d_in, const int* in_sizes, int n_in,
                              void* d_out, int out_size) {
    const float* q  = (const float*)d_in[0];
    const float* k  = (const float*)d_in[1];
    const float* v  = (const float*)d_in[2];
    const float* ck = (const float*)d_in[3];
    const float* cv = (const float*)d_in[4];
    const float* fc = (const float*)d_in[5];
    const float* fs = (const float*)d_in[6];
    float* out = (float*)d_out;

    (void)in_sizes; (void)n_in; (void)out_size;

    int nPairs = S * H * 32;
    rope_prep<<<(nPairs + 255) / 256, 256>>>(q, k, fc, fs);

    const int smem_bytes = (BN * KSTRIDE + BN * VSTRIDE + BM * KSTRIDE) * (int)sizeof(float);
    cudaFuncSetAttribute(attn_kernel, cudaFuncAttributeMaxDynamicSharedMemorySize, smem_bytes);
    dim3 grid(S / BM, H);
    attn_kernel<<<grid, 128, smem_bytes>>>(v, ck, cv, out);
}

// round 2
// speedup vs baseline: 1.2864x; 1.2864x over previous
#include <cuda_runtime.h>
#include <cstdint>

// Problem constants (from reference)
#define H 16
#define D 64
#define S 1024
#define START_FRAME 9728
#define NKV 8192        // attention window length
#define CACHE_OFF 2560  // window j -> cache index 2560+j  (for j < SPLIT)
#define SPLIT 7168      // j >= SPLIT -> new tokens (j - SPLIT)
#define BM 64
#define BN 64
#define KSTRIDE 68
#define VSTRIDE 72
#define NSPLIT 8
#define TPS (NKV / BN / NSPLIT)   // 16 kv-tiles per split

// Scratch (allocation-free rule: __device__ globals)
__device__ float g_qr[S * H * D];
__device__ float g_kr[S * H * D];
__device__ float g_po[NSPLIT * S * H * D];   // unnormalized partial O
__device__ float g_m[NSPLIT * S * H];        // per-split log2-domain row max
__device__ float g_l[NSPLIT * S * H];        // per-split row denom

// ---------------------------------------------------------------------------
// RoPE prep: q_rope, k_rope into scratch. One thread per (s, h, pair).
// ---------------------------------------------------------------------------
__global__ void rope_prep(const float* __restrict__ q, const float* __restrict__ k,
                          const float* __restrict__ fc, const float* __restrict__ fs) {
    int idx = blockIdx.x * blockDim.x + threadIdx.x;  // S*H*32 pairs
    if (idx >= S * H * 32) return;
    int p = idx & 31;
    int h = (idx >> 5) & 15;
    int s = idx >> 9;
    int pos = START_FRAME + s;
    float c  = fc[pos * 64 + 2 * p];
    float sn = fs[pos * 64 + 2 * p];
    int base = (s * H + h) * D + 2 * p;
    float q1 = q[base], q2 = q[base + 1];
    g_qr[base]     = q1 * c - q2 * sn;
    g_qr[base + 1] = q2 * c + q1 * sn;
    float k1 = k[base], k2 = k[base + 1];
    g_kr[base]     = k1 * c - k2 * sn;
    g_kr[base + 1] = k2 * c + k1 * sn;
}

// ---------------------------------------------------------------------------
// Helpers
// ---------------------------------------------------------------------------
__device__ __forceinline__ uint32_t f2tf(float f) {
    uint32_t r;
    asm("cvt.rna.tf32.f32 %0, %1;" : "=r"(r) : "f"(f));
    return r;
}
__device__ __forceinline__ float f2tf_f(float f) { return __uint_as_float(f2tf(f)); }

__device__ __forceinline__ float ex2(float x) {
    float y;
    asm("ex2.approx.f32 %0, %1;" : "=f"(y) : "f"(x));
    return y;
}

__device__ __forceinline__ void mma_tf32(float* c,
                                         uint32_t a0, uint32_t a1, uint32_t a2, uint32_t a3,
                                         uint32_t b0, uint32_t b1) {
    asm volatile(
        "mma.sync.aligned.m16n8k8.row.col.f32.tf32.tf32.f32 "
        "{%0,%1,%2,%3}, {%4,%5,%6,%7}, {%8,%9}, {%0,%1,%2,%3};\n"
        : "+f"(c[0]), "+f"(c[1]), "+f"(c[2]), "+f"(c[3])
        : "r"(a0), "r"(a1), "r"(a2), "r"(a3), "r"(b0), "r"(b1));
}

// ---------------------------------------------------------------------------
// Flash attention (split-KV), tf32 mma.sync.
// grid = (S/BM, H, NSPLIT), block = 128 (4 warps).
// smem: K tile [64][68], V tile [64][72], P/Q-stage tile [64][68]
// ---------------------------------------------------------------------------
__global__ __launch_bounds__(128, 4) void attn_kernel(
    const float* __restrict__ v_in,
    const float* __restrict__ cache_k,
    const float* __restrict__ cache_v)
{
    extern __shared__ float smem[];
    float* ksm = smem;                      // BN * KSTRIDE
    float* vsm = ksm + BN * KSTRIDE;        // BN * VSTRIDE
    float* psm = vsm + BN * VSTRIDE;        // BM * KSTRIDE

    const int h     = blockIdx.y;
    const int q0    = blockIdx.x * BM;
    const int split = blockIdx.z;
    const int tid   = threadIdx.x;
    const int warp  = tid >> 5;
    const int lane  = tid & 31;
    const int gid   = lane >> 2;   // groupID (row within fragment)
    const int tig   = lane & 3;    // threadID_in_group (col within fragment)

    // source select once per CTA: splits 0..6 fully in rolled cache,
    // split 7 fully in the new-token region (SPLIT = 7*1024).
    const float* kp; const float* vp; int base0;
    if (split < SPLIT / (TPS * BN)) {
        kp = cache_k; vp = cache_v; base0 = CACHE_OFF + split * (TPS * BN);
    } else {
        kp = g_kr; vp = v_in; base0 = 0;
    }

    // scale * log2(e) folded into Q -> scores live in log2 domain
    const float SCALE_LOG2E = 1.4426950408889634f * 0.125f;

    // ---- stage Q tile into psm, build per-warp tf32 A-fragments ----
    for (int i = tid; i < BM * 16; i += 128) {  // float4 granules
        int r = i >> 4, c4 = (i & 15) << 2;
        float4 qv = *(const float4*)&g_qr[((q0 + r) * H + h) * D + c4];
        *(float4*)&psm[r * KSTRIDE + c4] = qv;
    }
    __syncthreads();

    uint32_t qa[8][4];
    {
        int r0 = warp * 16 + gid;
        #pragma unroll
        for (int kk = 0; kk < 8; kk++) {
            int c0 = kk * 8 + tig;
            qa[kk][0] = f2tf(psm[r0 * KSTRIDE + c0] * SCALE_LOG2E);
            qa[kk][1] = f2tf(psm[(r0 + 8) * KSTRIDE + c0] * SCALE_LOG2E);
            qa[kk][2] = f2tf(psm[r0 * KSTRIDE + c0 + 4] * SCALE_LOG2E);
            qa[kk][3] = f2tf(psm[(r0 + 8) * KSTRIDE + c0 + 4] * SCALE_LOG2E);
        }
    }

    float o[8][4];
    #pragma unroll
    for (int i = 0; i < 8; i++) { o[i][0] = 0.f; o[i][1] = 0.f; o[i][2] = 0.f; o[i][3] = 0.f; }
    float M0 = -1e30f, M1 = -1e30f, L0 = 0.f, L1 = 0.f;

    for (int jt = 0; jt < TPS; jt++) {
        int rowbase = base0 + jt * BN;

        // ---- load K,V tiles (tf32-rounded at the copy) ----
        for (int i = tid; i < BN * 16; i += 128) {
            int r = i >> 4, c4 = (i & 15) << 2;
            int goff = ((rowbase + r) * H + h) * D + c4;
            float4 kv = *(const float4*)&kp[goff];
            *(float4*)&ksm[r * KSTRIDE + c4] =
                make_float4(f2tf_f(kv.x), f2tf_f(kv.y), f2tf_f(kv.z), f2tf_f(kv.w));
            float4 vv = *(const float4*)&vp[goff];
            *(float4*)&vsm[r * VSTRIDE + c4] =
                make_float4(f2tf_f(vv.x), f2tf_f(vv.y), f2tf_f(vv.z), f2tf_f(vv.w));
        }
        __syncthreads();

        // ---- S = Q * K^T (in log2 domain) ----
        float sacc[8][4];
        #pragma unroll
        for (int i = 0; i < 8; i++) { sacc[i][0] = 0.f; sacc[i][1] = 0.f; sacc[i][2] = 0.f; sacc[i][3] = 0.f; }
        #pragma unroll
        for (int kk = 0; kk < 8; kk++) {
            #pragma unroll
            for (int nn = 0; nn < 8; nn++) {
                uint32_t b0 = __float_as_uint(ksm[(nn * 8 + gid) * KSTRIDE + kk * 8 + tig]);
                uint32_t b1 = __float_as_uint(ksm[(nn * 8 + gid) * KSTRIDE + kk * 8 + tig + 4]);
                mma_tf32(sacc[nn], qa[kk][0], qa[kk][1], qa[kk][2], qa[kk][3], b0, b1);
            }
        }

        // ---- online softmax (base-2) ----
        float mx0 = -1e30f, mx1 = -1e30f;
        #pragma unroll
        for (int nn = 0; nn < 8; nn++) {
            mx0 = fmaxf(mx0, fmaxf(sacc[nn][0], sacc[nn][1]));
            mx1 = fmaxf(mx1, fmaxf(sacc[nn][2], sacc[nn][3]));
        }
        mx0 = fmaxf(mx0, __shfl_xor_sync(0xffffffffu, mx0, 1));
        mx0 = fmaxf(mx0, __shfl_xor_sync(0xffffffffu, mx0, 2));
        mx1 = fmaxf(mx1, __shfl_xor_sync(0xffffffffu, mx1, 1));
        mx1 = fmaxf(mx1, __shfl_xor_sync(0xffffffffu, mx1, 2));
        float nm0 = fmaxf(M0, mx0), nm1 = fmaxf(M1, mx1);
        float sc0 = ex2(M0 - nm0), sc1 = ex2(M1 - nm1);
        M0 = nm0; M1 = nm1;

        float ls0 = 0.f, ls1 = 0.f;
        {
            int r0 = warp * 16 + gid;
            #pragma unroll
            for (int nn = 0; nn < 8; nn++) {
                float p0 = ex2(sacc[nn][0] - M0);
                float p1 = ex2(sacc[nn][1] - M0);
                float p2 = ex2(sacc[nn][2] - M1);
                float p3 = ex2(sacc[nn][3] - M1);
                ls0 += p0 + p1;
                ls1 += p2 + p3;
                int cb = nn * 8 + 2 * tig;
                *(float2*)&psm[r0 * KSTRIDE + cb]       = make_float2(f2tf_f(p0), f2tf_f(p1));
                *(float2*)&psm[(r0 + 8) * KSTRIDE + cb] = make_float2(f2tf_f(p2), f2tf_f(p3));
            }
        }
        ls0 += __shfl_xor_sync(0xffffffffu, ls0, 1);
        ls0 += __shfl_xor_sync(0xffffffffu, ls0, 2);
        ls1 += __shfl_xor_sync(0xffffffffu, ls1, 1);
        ls1 += __shfl_xor_sync(0xffffffffu, ls1, 2);
        L0 = L0 * sc0 + ls0;
        L1 = L1 * sc1 + ls1;
        #pragma unroll
        for (int nn = 0; nn < 8; nn++) {
            o[nn][0] *= sc0; o[nn][1] *= sc0; o[nn][2] *= sc1; o[nn][3] *= sc1;
        }

        __syncwarp();  // P: own-row cross-lane visibility within warp

        // ---- O += P * V ----
        {
            int r0 = warp * 16 + gid;
            #pragma unroll
            for (int kk = 0; kk < 8; kk++) {
                uint32_t a0 = __float_as_uint(psm[r0 * KSTRIDE + kk * 8 + tig]);
                uint32_t a1 = __float_as_uint(psm[(r0 + 8) * KSTRIDE + kk * 8 + tig]);
                uint32_t a2 = __float_as_uint(psm[r0 * KSTRIDE + kk * 8 + tig + 4]);
                uint32_t a3 = __float_as_uint(psm[(r0 + 8) * KSTRIDE + kk * 8 + tig + 4]);
                #pragma unroll
                for (int nn = 0; nn < 8; nn++) {
                    uint32_t b0 = __float_as_uint(vsm[(kk * 8 + tig) * VSTRIDE + nn * 8 + gid]);
                    uint32_t b1 = __float_as_uint(vsm[(kk * 8 + tig + 4) * VSTRIDE + nn * 8 + gid]);
                    mma_tf32(o[nn], a0, a1, a2, a3, b0, b1);
                }
            }
        }
        __syncthreads();  // before next tile overwrites ksm/vsm (and psm reads done)
    }

    // ---- write unnormalized partials + (M, L) per row ----
    int r0 = q0 + warp * 16 + gid;              // global query row (and r0+8)
    size_t pbase = ((size_t)split * S) * H;
    #pragma unroll
    for (int nn = 0; nn < 8; nn++) {
        int cb = nn * 8 + 2 * tig;
        *(float2*)&g_po[(pbase + (size_t)r0 * H + h) * D + cb] =
            make_float2(o[nn][0], o[nn][1]);
        *(float2*)&g_po[(pbase + (size_t)(r0 + 8) * H + h) * D + cb] =
            make_float2(o[nn][2], o[nn][3]);
    }
    if (tig == 0) {  // M/L uniform across the 4 tig lanes after shfl reduce
        g_m[pbase + (size_t)r0 * H + h]       = M0;
        g_m[pbase + (size_t)(r0 + 8) * H + h] = M1;
        g_l[pbase + (size_t)r0 * H + h]       = L0;
        g_l[pbase + (size_t)(r0 + 8) * H + h] = L1;
    }
}

// ---------------------------------------------------------------------------
// Split reduction: combine NSPLIT partials per (s, h), normalize, write out.
// out[s, h*64+d];  idx = s*1024 + h*64 + d
// ---------------------------------------------------------------------------
__global__ __launch_bounds__(256) void reduce_kernel(float* __restrict__ out) {
    int idx = blockIdx.x * blockDim.x + threadIdx.x;
    if (idx >= S * H * D) return;
    int d = idx & 63;
    int h = (idx >> 6) & 15;
    int s = idx >> 10;
    int mlb = s * H + h;

    float Ms[NSPLIT];
    float m = -1e30f;
    #pragma unroll
    for (int i = 0; i < NSPLIT; i++) {
        Ms[i] = g_m[i * (S * H) + mlb];
        m = fmaxf(m, Ms[i]);
    }
    float num = 0.f, den = 0.f;
    #pragma unroll
    for (int i = 0; i < NSPLIT; i++) {
        float w = ex2(Ms[i] - m);
        num += g_po[(((size_t)i * S + s) * H + h) * D + d] * w;
        den += g_l[i * (S * H) + mlb] * w;
    }
    out[idx] = num / den;
}

// ---------------------------------------------------------------------------
extern "C" void kernel_launch(void* const* d_in, const int* in_sizes, int n_in,
                              void* d_out, int out_size) {
    const float* q  = (const float*)d_in[0];
    const float* k  = (const float*)d_in[1];
    const float* v  = (const float*)d_in[2];
    const float* ck = (const float*)d_in[3];
    const float* cv = (const float*)d_in[4];
    const float* fc = (const float*)d_in[5];
    const float* fs = (const float*)d_in[6];
    float* out = (float*)d_out;

    (void)in_sizes; (void)n_in; (void)out_size;

    int nPairs = S * H * 32;
    rope_prep<<<(nPairs + 255) / 256, 256>>>(q, k, fc, fs);

    const int smem_bytes = (BN * KSTRIDE + BN * VSTRIDE + BM * KSTRIDE) * (int)sizeof(float);
    cudaFuncSetAttribute(attn_kernel, cudaFuncAttributeMaxDynamicSharedMemorySize, smem_bytes);
    dim3 grid(S / BM, H, NSPLIT);
    attn_kernel<<<grid, 128, smem_bytes>>>(v, ck, cv);

    reduce_kernel<<<(S * H * D + 255) / 256, 256>>>(out);
}

// round 4
// speedup vs baseline: 2.6900x; 2.0911x over previous
#include <cuda_runtime.h>
#include <cuda_fp16.h>
#include <cstdint>

// Problem constants
#define H 16
#define D 64
#define S 1024
#define START_FRAME 9728
#define NKV 8192
#define CACHE_OFF 2560
#define SPLIT 7168
#define BM 128
#define BN 64
#define NSPLIT 4
#define TPT (NKV / BN / NSPLIT)   // 32 kv tiles per CTA
#define KS 72                     // smem row stride in halves (144B: conflict-free)

// Scratch (__device__ globals per allocation rules)
__device__ float  g_qr[S * H * D];            // roped Q, pre-scaled by log2e/8
__device__ __half g_kh[(size_t)H * NKV * D];  // merged window K, fp16, [h][key][d]
__device__ __half g_vt[(size_t)H * D * NKV];  // merged window V^T, fp16, [h][d][key]
__device__ float  g_po[NSPLIT * S * H * D];   // partial O (unnormalized)
__device__ float  g_l[NSPLIT * S * H];        // partial denom

// ---------------------------------------------------------------------------
// Helpers
// ---------------------------------------------------------------------------
__device__ __forceinline__ float ex2(float x) {
    float y;
    asm("ex2.approx.f32 %0, %1;" : "=f"(y) : "f"(x));
    return y;
}
__device__ __forceinline__ uint32_t h2u(__half2 v) {
    return *reinterpret_cast<uint32_t*>(&v);
}
__device__ __forceinline__ void mma_f16(float* c, const uint32_t* a, uint32_t b0, uint32_t b1) {
    asm volatile(
        "mma.sync.aligned.m16n8k16.row.col.f32.f16.f16.f32 "
        "{%0,%1,%2,%3}, {%4,%5,%6,%7}, {%8,%9}, {%0,%1,%2,%3};\n"
        : "+f"(c[0]), "+f"(c[1]), "+f"(c[2]), "+f"(c[3])
        : "r"(a[0]), "r"(a[1]), "r"(a[2]), "r"(a[3]), "r"(b0), "r"(b1));
}

// ---------------------------------------------------------------------------
// Prep 1: RoPE. Q -> g_qr (fp32, scaled by log2e/8). New K -> g_kh[h][SPLIT+s].
// ---------------------------------------------------------------------------
__global__ void rope_prep(const float* __restrict__ q, const float* __restrict__ k,
                          const float* __restrict__ fc, const float* __restrict__ fs) {
    const float SC = 1.4426950408889634f * 0.125f;
    int idx = blockIdx.x * blockDim.x + threadIdx.x;   // S*H*32
    if (idx >= S * H * 32) return;
    int p = idx & 31;
    int h = (idx >> 5) & 15;
    int s = idx >> 9;
    int pos = START_FRAME + s;
    float c  = fc[pos * 64 + 2 * p];
    float sn = fs[pos * 64 + 2 * p];
    int base = (s * H + h) * D + 2 * p;
    float q1 = q[base], q2 = q[base + 1];
    g_qr[base]     = (q1 * c - q2 * sn) * SC;
    g_qr[base + 1] = (q2 * c + q1 * sn) * SC;
    float k1 = k[base], k2 = k[base + 1];
    *(__half2*)&g_kh[((size_t)h * NKV + SPLIT + s) * D + 2 * p] =
        __floats2half2_rn(k1 * c - k2 * sn, k2 * c + k1 * sn);
}

// ---------------------------------------------------------------------------
// Prep 2: cache K (rolled region) -> g_kh[h][0..SPLIT), fp16
// ---------------------------------------------------------------------------
__global__ void conv_k(const float* __restrict__ cache_k) {
    int idx = blockIdx.x * blockDim.x + threadIdx.x;   // SPLIT*H*32
    if (idx >= SPLIT * H * 32) return;
    int p = idx & 31;
    int h = (idx >> 5) & 15;
    int j = idx >> 9;
    const float* src = &cache_k[(size_t)(CACHE_OFF + j) * (H * D) + h * D + 2 * p];
    *(__half2*)&g_kh[((size_t)h * NKV + j) * D + 2 * p] = __floats2half2_rn(src[0], src[1]);
}

// ---------------------------------------------------------------------------
// Prep 3: V (merged window) transposed -> g_vt[h][d][key], fp16. grid (128, 16)
// ---------------------------------------------------------------------------
__global__ __launch_bounds__(256) void transpose_v(const float* __restrict__ v_in,
                                                   const float* __restrict__ cache_v) {
    __shared__ float t[64][65];
    int kt = blockIdx.x, h = blockIdx.y, tid = threadIdx.x;
    for (int i = tid; i < 1024; i += 256) {
        int r = i >> 4, c4 = (i & 15) << 2;
        int key = kt * 64 + r;
        const float* src = (key < SPLIT)
            ? &cache_v[(size_t)(CACHE_OFF + key) * (H * D) + h * D + c4]
            : &v_in[(size_t)(key - SPLIT) * (H * D) + h * D + c4];
        float4 x = *(const float4*)src;
        t[r][c4] = x.x; t[r][c4 + 1] = x.y; t[r][c4 + 2] = x.z; t[r][c4 + 3] = x.w;
    }
    __syncthreads();
    for (int i = tid; i < 1024; i += 256) {
        int d = i >> 4, k4 = (i & 15) << 2;
        size_t dst = (size_t)(h * 64 + d) * NKV + kt * 64 + k4;
        *(__half2*)&g_vt[dst]     = __floats2half2_rn(t[k4][d], t[k4 + 1][d]);
        *(__half2*)&g_vt[dst + 2] = __floats2half2_rn(t[k4 + 2][d], t[k4 + 3][d]);
    }
}

// ---------------------------------------------------------------------------
// Flash attention, fp16 mma.sync m16n8k16.
// grid = (S/BM=8, H=16, NSPLIT=4) = 512 CTAs, block = 128 (4 warps x 32 rows).
// No max-subtraction: scores (log2 domain) are bounded (|s| <~ 8), p = 2^s
// fits fp16 comfortably; O accumulates in fp32, L in fp32 registers.
// ---------------------------------------------------------------------------
struct Tile { int4 k[4], v[4]; };

__device__ __forceinline__ void ldg_k(Tile& t, int tid, int h, int kt) {
    const int4* ksrc = (const int4*)&g_kh[((size_t)h * NKV + (size_t)kt * BN) * D];
    #pragma unroll
    for (int g = 0; g < 4; g++) t.k[g] = ksrc[tid + g * 128];   // contiguous 8KB
}
__device__ __forceinline__ void ldg_v(Tile& t, int tid, int h, int kt) {
    #pragma unroll
    for (int g = 0; g < 4; g++) {
        int idx = tid + g * 128;
        int d = idx >> 3, c = idx & 7;
        t.v[g] = *(const int4*)&g_vt[(size_t)(h * 64 + d) * NKV + kt * BN + c * 8];
    }
}

__global__ __launch_bounds__(128, 2) void attn_fp16() {
    __shared__ __align__(16) __half ksm[2][BN * KS];
    __shared__ __align__(16) __half vsm[2][BN * KS];

    const int h    = blockIdx.y;
    const int q0   = blockIdx.x * BM;
    const int split = blockIdx.z;
    const int tid  = threadIdx.x;
    const int warp = tid >> 5;
    const int lane = tid & 31;
    const int gid  = lane >> 2;
    const int tig  = lane & 3;
    const int kt0  = split * TPT;

    // ---- Q A-fragments (fp32 gmem -> half2 regs), rows r0, r0+8 per m-tile ----
    uint32_t qa[2][4][4];
    #pragma unroll
    for (int mt = 0; mt < 2; mt++) {
        int r0 = q0 + warp * 32 + mt * 16 + gid;
        const float* qrow0 = &g_qr[(size_t)r0 * (H * D) + h * D];
        const float* qrow1 = &g_qr[(size_t)(r0 + 8) * (H * D) + h * D];
        #pragma unroll
        for (int kk = 0; kk < 4; kk++) {
            int c = kk * 16 + 2 * tig;
            float2 x0 = *(const float2*)&qrow0[c];
            float2 x1 = *(const float2*)&qrow1[c];
            float2 x2 = *(const float2*)&qrow0[c + 8];
            float2 x3 = *(const float2*)&qrow1[c + 8];
            qa[mt][kk][0] = h2u(__floats2half2_rn(x0.x, x0.y));
            qa[mt][kk][1] = h2u(__floats2half2_rn(x1.x, x1.y));
            qa[mt][kk][2] = h2u(__floats2half2_rn(x2.x, x2.y));
            qa[mt][kk][3] = h2u(__floats2half2_rn(x3.x, x3.y));
        }
    }

    float o[2][8][4];
    #pragma unroll
    for (int mt = 0; mt < 2; mt++)
        #pragma unroll
        for (int nn = 0; nn < 8; nn++)
            o[mt][nn][0] = o[mt][nn][1] = o[mt][nn][2] = o[mt][nn][3] = 0.f;
    float Lr[2][2] = {{0.f, 0.f}, {0.f, 0.f}};

    // ---- prologue: tile 0 into buffer 0 ----
    Tile t;
    ldg_k(t, tid, h, kt0);
    ldg_v(t, tid, h, kt0);
    {
        #pragma unroll
        for (int g = 0; g < 4; g++) {
            int idx = tid + g * 128;
            int r = idx >> 3, c = idx & 7;
            *(int4*)&ksm[0][r * KS + c * 8] = t.k[g];
            *(int4*)&vsm[0][r * KS + c * 8] = t.v[g];
        }
    }
    __syncthreads();

    for (int j = 0; j < TPT; j++) {
        const int cur = j & 1;
        const bool more = (j + 1 < TPT);

        if (more) ldg_k(t, tid, h, kt0 + j + 1);   // hide behind MMA1

        // ---- MMA1: S = Q * K^T (log2 domain) ----
        float sacc[2][8][4];
        #pragma unroll
        for (int mt = 0; mt < 2; mt++)
            #pragma unroll
            for (int nn = 0; nn < 8; nn++)
                sacc[mt][nn][0] = sacc[mt][nn][1] = sacc[mt][nn][2] = sacc[mt][nn][3] = 0.f;
        const __half* kb = ksm[cur];
        #pragma unroll
        for (int nn = 0; nn < 8; nn++) {
            int row = nn * 8 + gid;
            #pragma unroll
            for (int kk = 0; kk < 4; kk++) {
                uint32_t b0 = *(const uint32_t*)&kb[row * KS + kk * 16 + 2 * tig];
                uint32_t b1 = *(const uint32_t*)&kb[row * KS + kk * 16 + 8 + 2 * tig];
                mma_f16(sacc[0][nn], qa[0][kk], b0, b1);
                mma_f16(sacc[1][nn], qa[1][kk], b0, b1);
            }
        }

        // ---- softmax in registers: p = 2^s; accumulate L; build MMA2 A-frags ----
        uint32_t pa[2][4][4];
        #pragma unroll
        for (int mt = 0; mt < 2; mt++) {
            #pragma unroll
            for (int kk = 0; kk < 4; kk++) {
                float p00 = ex2(sacc[mt][2 * kk][0]);
                float p01 = ex2(sacc[mt][2 * kk][1]);
                float p02 = ex2(sacc[mt][2 * kk][2]);
                float p03 = ex2(sacc[mt][2 * kk][3]);
                float p10 = ex2(sacc[mt][2 * kk + 1][0]);
                float p11 = ex2(sacc[mt][2 * kk + 1][1]);
                float p12 = ex2(sacc[mt][2 * kk + 1][2]);
                float p13 = ex2(sacc[mt][2 * kk + 1][3]);
                Lr[mt][0] += (p00 + p01) + (p10 + p11);
                Lr[mt][1] += (p02 + p03) + (p12 + p13);
                pa[mt][kk][0] = h2u(__floats2half2_rn(p00, p01));  // a0: row gid,  k 0-7
                pa[mt][kk][1] = h2u(__floats2half2_rn(p02, p03));  // a1: row gid+8, k 0-7
                pa[mt][kk][2] = h2u(__floats2half2_rn(p10, p11));  // a2: row gid,  k 8-15
                pa[mt][kk][3] = h2u(__floats2half2_rn(p12, p13));  // a3: row gid+8, k 8-15
            }
        }

        if (more) ldg_v(t, tid, h, kt0 + j + 1);   // hide behind MMA2

        // ---- MMA2: O += P * V (V^T in smem: [dim][key]) ----
        const __half* vb = vsm[cur];
        #pragma unroll
        for (int nn = 0; nn < 8; nn++) {
            int row = nn * 8 + gid;
            #pragma unroll
            for (int kk = 0; kk < 4; kk++) {
                uint32_t b0 = *(const uint32_t*)&vb[row * KS + kk * 16 + 2 * tig];
                uint32_t b1 = *(const uint32_t*)&vb[row * KS + kk * 16 + 8 + 2 * tig];
                mma_f16(o[0][nn], pa[0][kk], b0, b1);
                mma_f16(o[1][nn], pa[1][kk], b0, b1);
            }
        }

        if (more) {
            #pragma unroll
            for (int g = 0; g < 4; g++) {
                int idx = tid + g * 128;
                int r = idx >> 3, c = idx & 7;
                *(int4*)&ksm[1 - cur][r * KS + c * 8] = t.k[g];
                *(int4*)&vsm[1 - cur][r * KS + c * 8] = t.v[g];
            }
            __syncthreads();
        }
    }

    // ---- epilogue: reduce L over the 4 tig lanes, write partials ----
    #pragma unroll
    for (int mt = 0; mt < 2; mt++) {
        Lr[mt][0] += __shfl_xor_sync(0xffffffffu, Lr[mt][0], 1);
        Lr[mt][0] += __shfl_xor_sync(0xffffffffu, Lr[mt][0], 2);
        Lr[mt][1] += __shfl_xor_sync(0xffffffffu, Lr[mt][1], 1);
        Lr[mt][1] += __shfl_xor_sync(0xffffffffu, Lr[mt][1], 2);

        int r = q0 + warp * 32 + mt * 16 + gid;
        size_t b0 = ((size_t)split * S + r) * (H * D) + h * 64;
        size_t b1 = ((size_t)split * S + r + 8) * (H * D) + h * 64;
        #pragma unroll
        for (int nn = 0; nn < 8; nn++) {
            *(float2*)&g_po[b0 + nn * 8 + 2 * tig] = make_float2(o[mt][nn][0], o[mt][nn][1]);
            *(float2*)&g_po[b1 + nn * 8 + 2 * tig] = make_float2(o[mt][nn][2], o[mt][nn][3]);
        }
        if (tig == 0) {
            g_l[(size_t)split * (S * H) + (size_t)r * H + h]       = Lr[mt][0];
            g_l[(size_t)split * (S * H) + (size_t)(r + 8) * H + h] = Lr[mt][1];
        }
    }
}

// ---------------------------------------------------------------------------
// Merge splits: out = sum(po) / sum(l)   (no max shift — none used)
// ---------------------------------------------------------------------------
__global__ __launch_bounds__(256) void reduce_kernel(float* __restrict__ out) {
    int idx = blockIdx.x * blockDim.x + threadIdx.x;
    if (idx >= S * H * D) return;
    int h = (idx >> 6) & 15;
    int s = idx >> 10;
    int mlb = s * H + h;
    float num = 0.f, den = 0.f;
    #pragma unroll
    for (int i = 0; i < NSPLIT; i++) {
        num += g_po[(size_t)i * (S * H * D) + idx];
        den += g_l[(size_t)i * (S * H) + mlb];
    }
    out[idx] = num / den;
}

// ---------------------------------------------------------------------------
extern "C" void kernel_launch(void* const* d_in, const int* in_sizes, int n_in,
                              void* d_out, int out_size) {
    const float* q  = (const float*)d_in[0];
    const float* k  = (const float*)d_in[1];
    const float* v  = (const float*)d_in[2];
    const float* ck = (const float*)d_in[3];
    const float* cv = (const float*)d_in[4];
    const float* fc = (const float*)d_in[5];
    const float* fs = (const float*)d_in[6];
    float* out = (float*)d_out;
    (void)in_sizes; (void)n_in; (void)out_size;

    rope_prep<<<(S * H * 32 + 255) / 256, 256>>>(q, k, fc, fs);
    conv_k<<<(SPLIT * H * 32 + 255) / 256, 256>>>(ck);
    transpose_v<<<dim3(NKV / 64, H), 256>>>(v, cv);

    dim3 grid(S / BM, H, NSPLIT);
    attn_fp16<<<grid, 128>>>();

    reduce_kernel<<<(S * H * D + 255) / 256, 256>>>(out);
}

// round 5
// speedup vs baseline: 2.8059x; 1.0431x over previous
#include <cuda_runtime.h>
#include <cuda_fp16.h>
#include <cstdint>

// Problem constants
#define H 16
#define D 64
#define S 1024
#define START_FRAME 9728
#define NKV 8192
#define CACHE_OFF 2560
#define SPLIT 7168
#define BM 128
#define BN 64
#define NSPLIT 8
#define TPT (NKV / BN / NSPLIT)   // 16 kv tiles per CTA
#define KS 72                     // smem row stride in halves (144B: conflict-free)

// Scratch (__device__ globals per allocation rules)
__device__ __align__(16) float  g_qr[S * H * D];            // roped Q, scaled log2e/8
__device__ __align__(16) __half g_kh[(size_t)H * NKV * D];  // window K fp16 [h][key][d]
__device__ __align__(16) __half g_vt[(size_t)H * D * NKV];  // window V^T fp16 [h][d][key]
__device__ __align__(16) float  g_po[NSPLIT * S * H * D];   // partial O
__device__ __align__(16) float  g_l[NSPLIT * S * H];        // partial denom

// ---------------------------------------------------------------------------
// Helpers
// ---------------------------------------------------------------------------
__device__ __forceinline__ float ex2(float x) {
    float y;
    asm("ex2.approx.f32 %0, %1;" : "=f"(y) : "f"(x));
    return y;
}
__device__ __forceinline__ uint32_t h2u(__half2 v) {
    return *reinterpret_cast<uint32_t*>(&v);
}
__device__ __forceinline__ void mma_f16(float* c, const uint32_t* a, uint32_t b0, uint32_t b1) {
    asm volatile(
        "mma.sync.aligned.m16n8k16.row.col.f32.f16.f16.f32 "
        "{%0,%1,%2,%3}, {%4,%5,%6,%7}, {%8,%9}, {%0,%1,%2,%3};\n"
        : "+f"(c[0]), "+f"(c[1]), "+f"(c[2]), "+f"(c[3])
        : "r"(a[0]), "r"(a[1]), "r"(a[2]), "r"(a[3]), "r"(b0), "r"(b1));
}
__device__ __forceinline__ void cp16(uint32_t smem_addr, const void* gptr) {
    asm volatile("cp.async.cg.shared.global [%0], [%1], 16;"
                 :: "r"(smem_addr), "l"(gptr));
}
#define CP_COMMIT() asm volatile("cp.async.commit_group;" ::: "memory")
#define CP_WAIT(N)  asm volatile("cp.async.wait_group %0;" :: "n"(N) : "memory")

// ---------------------------------------------------------------------------
// Prep 1: RoPE. Q -> g_qr (fp32, scaled). New K -> g_kh[h][SPLIT+s].
// ---------------------------------------------------------------------------
__global__ void rope_prep(const float* __restrict__ q, const float* __restrict__ k,
                          const float* __restrict__ fc, const float* __restrict__ fs) {
    const float SC = 1.4426950408889634f * 0.125f;
    int idx = blockIdx.x * blockDim.x + threadIdx.x;
    if (idx >= S * H * 32) return;
    int p = idx & 31;
    int h = (idx >> 5) & 15;
    int s = idx >> 9;
    int pos = START_FRAME + s;
    float c  = fc[pos * 64 + 2 * p];
    float sn = fs[pos * 64 + 2 * p];
    int base = (s * H + h) * D + 2 * p;
    float q1 = q[base], q2 = q[base + 1];
    g_qr[base]     = (q1 * c - q2 * sn) * SC;
    g_qr[base + 1] = (q2 * c + q1 * sn) * SC;
    float k1 = k[base], k2 = k[base + 1];
    *(__half2*)&g_kh[((size_t)h * NKV + SPLIT + s) * D + 2 * p] =
        __floats2half2_rn(k1 * c - k2 * sn, k2 * c + k1 * sn);
}

// ---------------------------------------------------------------------------
// Prep 2: cache K (rolled region) -> g_kh[h][0..SPLIT), fp16
// ---------------------------------------------------------------------------
__global__ void conv_k(const float* __restrict__ cache_k) {
    int idx = blockIdx.x * blockDim.x + threadIdx.x;
    if (idx >= SPLIT * H * 32) return;
    int p = idx & 31;
    int h = (idx >> 5) & 15;
    int j = idx >> 9;
    const float* src = &cache_k[(size_t)(CACHE_OFF + j) * (H * D) + h * D + 2 * p];
    *(__half2*)&g_kh[((size_t)h * NKV + j) * D + 2 * p] = __floats2half2_rn(src[0], src[1]);
}

// ---------------------------------------------------------------------------
// Prep 3: V (merged window) transposed -> g_vt[h][d][key], fp16. grid (128, 16)
// ---------------------------------------------------------------------------
__global__ __launch_bounds__(256) void transpose_v(const float* __restrict__ v_in,
                                                   const float* __restrict__ cache_v) {
    __shared__ float t[64][65];
    int kt = blockIdx.x, h = blockIdx.y, tid = threadIdx.x;
    for (int i = tid; i < 1024; i += 256) {
        int r = i >> 4, c4 = (i & 15) << 2;
        int key = kt * 64 + r;
        const float* src = (key < SPLIT)
            ? &cache_v[(size_t)(CACHE_OFF + key) * (H * D) + h * D + c4]
            : &v_in[(size_t)(key - SPLIT) * (H * D) + h * D + c4];
        float4 x = *(const float4*)src;
        t[r][c4] = x.x; t[r][c4 + 1] = x.y; t[r][c4 + 2] = x.z; t[r][c4 + 3] = x.w;
    }
    __syncthreads();
    for (int i = tid; i < 1024; i += 256) {
        int d = i >> 4, k4 = (i & 15) << 2;
        size_t dst = (size_t)(h * 64 + d) * NKV + kt * 64 + k4;
        *(__half2*)&g_vt[dst]     = __floats2half2_rn(t[k4][d], t[k4 + 1][d]);
        *(__half2*)&g_vt[dst + 2] = __floats2half2_rn(t[k4 + 2][d], t[k4 + 3][d]);
    }
}

// ---------------------------------------------------------------------------
// Flash attention, fp16 mma.sync m16n8k16, cp.async double-buffered.
// grid = (8, 16, 8) = 1024 CTAs, block = 128 (4 warps x 32 q-rows), 3 CTAs/SM.
// ---------------------------------------------------------------------------
__shared__ __align__(16) __half ksm_[2][BN * KS];
// (declared inside kernel; placeholder comment)

__device__ __forceinline__ void prefetch_tile(uint32_t kbase, uint32_t vbase,
                                              int tid, int h, int kt) {
    const char* ksrc = (const char*)&g_kh[((size_t)h * NKV + (size_t)kt * BN) * D];
    #pragma unroll
    for (int g = 0; g < 4; g++) {
        int idx = tid + g * 128;
        int r = idx >> 3, c = idx & 7;
        cp16(kbase + (uint32_t)(r * KS + c * 8) * 2, ksrc + (size_t)idx * 16);
    }
    #pragma unroll
    for (int g = 0; g < 4; g++) {
        int idx = tid + g * 128;
        int d = idx >> 3, c = idx & 7;
        cp16(vbase + (uint32_t)(d * KS + c * 8) * 2,
             (const char*)&g_vt[(size_t)(h * 64 + d) * NKV + (size_t)kt * BN + c * 8]);
    }
}

__global__ __launch_bounds__(128, 3) void attn_fp16() {
    __shared__ __align__(16) __half ksm[2][BN * KS];
    __shared__ __align__(16) __half vsm[2][BN * KS];

    const int h     = blockIdx.y;
    const int q0    = blockIdx.x * BM;
    const int split = blockIdx.z;
    const int tid   = threadIdx.x;
    const int warp  = tid >> 5;
    const int lane  = tid & 31;
    const int gid   = lane >> 2;
    const int tig   = lane & 3;
    const int kt0   = split * TPT;

    uint32_t kaddr[2], vaddr[2];
    kaddr[0] = (uint32_t)__cvta_generic_to_shared(&ksm[0][0]);
    kaddr[1] = (uint32_t)__cvta_generic_to_shared(&ksm[1][0]);
    vaddr[0] = (uint32_t)__cvta_generic_to_shared(&vsm[0][0]);
    vaddr[1] = (uint32_t)__cvta_generic_to_shared(&vsm[1][0]);

    // prologue prefetch of tile 0 (overlaps Q fragment loads below)
    prefetch_tile(kaddr[0], vaddr[0], tid, h, kt0);
    CP_COMMIT();

    // ---- Q A-fragments ----
    uint32_t qa[2][4][4];
    #pragma unroll
    for (int mt = 0; mt < 2; mt++) {
        int r0 = q0 + warp * 32 + mt * 16 + gid;
        const float* qrow0 = &g_qr[(size_t)r0 * (H * D) + h * D];
        const float* qrow1 = &g_qr[(size_t)(r0 + 8) * (H * D) + h * D];
        #pragma unroll
        for (int kk = 0; kk < 4; kk++) {
            int c = kk * 16 + 2 * tig;
            float2 x0 = *(const float2*)&qrow0[c];
            float2 x1 = *(const float2*)&qrow1[c];
            float2 x2 = *(const float2*)&qrow0[c + 8];
            float2 x3 = *(const float2*)&qrow1[c + 8];
            qa[mt][kk][0] = h2u(__floats2half2_rn(x0.x, x0.y));
            qa[mt][kk][1] = h2u(__floats2half2_rn(x1.x, x1.y));
            qa[mt][kk][2] = h2u(__floats2half2_rn(x2.x, x2.y));
            qa[mt][kk][3] = h2u(__floats2half2_rn(x3.x, x3.y));
        }
    }

    float o[2][8][4];
    #pragma unroll
    for (int mt = 0; mt < 2; mt++)
        #pragma unroll
        for (int nn = 0; nn < 8; nn++)
            o[mt][nn][0] = o[mt][nn][1] = o[mt][nn][2] = o[mt][nn][3] = 0.f;
    float Lr[2][2] = {{0.f, 0.f}, {0.f, 0.f}};

    for (int j = 0; j < TPT; j++) {
        const int cur = j & 1;

        if (j + 1 < TPT) {
            prefetch_tile(kaddr[1 - cur], vaddr[1 - cur], tid, h, kt0 + j + 1);
            CP_COMMIT();
            CP_WAIT(1);          // tile j complete; tile j+1 may be in flight
        } else {
            CP_WAIT(0);
        }
        __syncthreads();         // publish tile j to all warps

        // ---- MMA1: S = Q * K^T (log2 domain) ----
        float sacc[2][8][4];
        #pragma unroll
        for (int mt = 0; mt < 2; mt++)
            #pragma unroll
            for (int nn = 0; nn < 8; nn++)
                sacc[mt][nn][0] = sacc[mt][nn][1] = sacc[mt][nn][2] = sacc[mt][nn][3] = 0.f;
        const __half* kb = ksm[cur];
        #pragma unroll
        for (int nn = 0; nn < 8; nn++) {
            int row = nn * 8 + gid;
            #pragma unroll
            for (int kk = 0; kk < 4; kk++) {
                uint32_t b0 = *(const uint32_t*)&kb[row * KS + kk * 16 + 2 * tig];
                uint32_t b1 = *(const uint32_t*)&kb[row * KS + kk * 16 + 8 + 2 * tig];
                mma_f16(sacc[0][nn], qa[0][kk], b0, b1);
                mma_f16(sacc[1][nn], qa[1][kk], b0, b1);
            }
        }

        // ---- softmax in registers: p = 2^s; accumulate L; build MMA2 A-frags ----
        uint32_t pa[2][4][4];
        #pragma unroll
        for (int mt = 0; mt < 2; mt++) {
            #pragma unroll
            for (int kk = 0; kk < 4; kk++) {
                float p00 = ex2(sacc[mt][2 * kk][0]);
                float p01 = ex2(sacc[mt][2 * kk][1]);
                float p02 = ex2(sacc[mt][2 * kk][2]);
                float p03 = ex2(sacc[mt][2 * kk][3]);
                float p10 = ex2(sacc[mt][2 * kk + 1][0]);
                float p11 = ex2(sacc[mt][2 * kk + 1][1]);
                float p12 = ex2(sacc[mt][2 * kk + 1][2]);
                float p13 = ex2(sacc[mt][2 * kk + 1][3]);
                Lr[mt][0] += (p00 + p01) + (p10 + p11);
                Lr[mt][1] += (p02 + p03) + (p12 + p13);
                pa[mt][kk][0] = h2u(__floats2half2_rn(p00, p01));
                pa[mt][kk][1] = h2u(__floats2half2_rn(p02, p03));
                pa[mt][kk][2] = h2u(__floats2half2_rn(p10, p11));
                pa[mt][kk][3] = h2u(__floats2half2_rn(p12, p13));
            }
        }

        // ---- MMA2: O += P * V ----
        const __half* vb = vsm[cur];
        #pragma unroll
        for (int nn = 0; nn < 8; nn++) {
            int row = nn * 8 + gid;
            #pragma unroll
            for (int kk = 0; kk < 4; kk++) {
                uint32_t b0 = *(const uint32_t*)&vb[row * KS + kk * 16 + 2 * tig];
                uint32_t b1 = *(const uint32_t*)&vb[row * KS + kk * 16 + 8 + 2 * tig];
                mma_f16(o[0][nn], pa[0][kk], b0, b1);
                mma_f16(o[1][nn], pa[1][kk], b0, b1);
            }
        }
        __syncthreads();   // all warps done reading buf[cur] before j+1 overwrites it
    }

    // ---- epilogue ----
    #pragma unroll
    for (int mt = 0; mt < 2; mt++) {
        Lr[mt][0] += __shfl_xor_sync(0xffffffffu, Lr[mt][0], 1);
        Lr[mt][0] += __shfl_xor_sync(0xffffffffu, Lr[mt][0], 2);
        Lr[mt][1] += __shfl_xor_sync(0xffffffffu, Lr[mt][1], 1);
        Lr[mt][1] += __shfl_xor_sync(0xffffffffu, Lr[mt][1], 2);

        int r = q0 + warp * 32 + mt * 16 + gid;
        size_t b0 = ((size_t)split * S + r) * (H * D) + h * 64;
        size_t b1 = ((size_t)split * S + r + 8) * (H * D) + h * 64;
        #pragma unroll
        for (int nn = 0; nn < 8; nn++) {
            *(float2*)&g_po[b0 + nn * 8 + 2 * tig] = make_float2(o[mt][nn][0], o[mt][nn][1]);
            *(float2*)&g_po[b1 + nn * 8 + 2 * tig] = make_float2(o[mt][nn][2], o[mt][nn][3]);
        }
        if (tig == 0) {
            g_l[(size_t)split * (S * H) + (size_t)r * H + h]       = Lr[mt][0];
            g_l[(size_t)split * (S * H) + (size_t)(r + 8) * H + h] = Lr[mt][1];
        }
    }
}

// ---------------------------------------------------------------------------
// Merge splits (float4): out = sum(po) / sum(l)
// ---------------------------------------------------------------------------
__global__ __launch_bounds__(256) void reduce_kernel(float* __restrict__ out) {
    int i4 = blockIdx.x * blockDim.x + threadIdx.x;
    if (i4 >= S * H * D / 4) return;
    int idx = i4 * 4;
    int h = (idx >> 6) & 15;
    int s = idx >> 10;
    int mlb = s * H + h;
    float4 num = make_float4(0.f, 0.f, 0.f, 0.f);
    float den = 0.f;
    #pragma unroll
    for (int i = 0; i < NSPLIT; i++) {
        float4 p = *(const float4*)&g_po[(size_t)i * (S * H * D) + idx];
        num.x += p.x; num.y += p.y; num.z += p.z; num.w += p.w;
        den += g_l[(size_t)i * (S * H) + mlb];
    }
    float r = 1.f / den;
    *(float4*)&out[idx] = make_float4(num.x * r, num.y * r, num.z * r, num.w * r);
}

// ---------------------------------------------------------------------------
extern "C" void kernel_launch(void* const* d_in, const int* in_sizes, int n_in,
                              void* d_out, int out_size) {
    const float* q  = (const float*)d_in[0];
    const float* k  = (const float*)d_in[1];
    const float* v  = (const float*)d_in[2];
    const float* ck = (const float*)d_in[3];
    const float* cv = (const float*)d_in[4];
    const float* fc = (const float*)d_in[5];
    const float* fs = (const float*)d_in[6];
    float* out = (float*)d_out;
    (void)in_sizes; (void)n_in; (void)out_size;

    rope_prep<<<(S * H * 32 + 255) / 256, 256>>>(q, k, fc, fs);
    conv_k<<<(SPLIT * H * 32 + 255) / 256, 256>>>(ck);
    transpose_v<<<dim3(NKV / 64, H), 256>>>(v, cv);

    dim3 grid(S / BM, H, NSPLIT);
    attn_fp16<<<grid, 128>>>();

    reduce_kernel<<<(S * H * D / 4 + 255) / 256, 256>>>(out);
}

// round 6
// speedup vs baseline: 2.9406x; 1.0480x over previous
#include <cuda_runtime.h>
#include <cuda_fp16.h>
#include <cstdint>

// Problem constants
#define H 16
#define D 64
#define S 1024
#define START_FRAME 9728
#define NKV 8192
#define CACHE_OFF 2560
#define SPLIT 7168
#define BM 64
#define BN 64
#define NSPLIT 4
#define TPT (NKV / BN / NSPLIT)   // 32 kv tiles per CTA
#define KS 72                     // smem row stride in halves (144B, conflict-free)
#define TILE_HALVES (BN * KS)     // 4608 halves = 9216 B per tile

// Scratch (__device__ globals per allocation rules)
__device__ __align__(16) float  g_qr[S * H * D];            // roped Q, scaled log2e/8
__device__ __align__(16) __half g_kh[(size_t)H * NKV * D];  // window K fp16 [h][key][d]
__device__ __align__(16) __half g_vt[(size_t)H * D * NKV];  // window V^T fp16 [h][d][key]
__device__ __align__(16) float  g_po[NSPLIT * S * H * D];   // partial O
__device__ __align__(16) float  g_l[NSPLIT * S * H];        // partial denom

// ---------------------------------------------------------------------------
// Helpers
// ---------------------------------------------------------------------------
__device__ __forceinline__ float ex2(float x) {
    float y;
    asm("ex2.approx.f32 %0, %1;" : "=f"(y) : "f"(x));
    return y;
}
__device__ __forceinline__ uint32_t h2u(__half2 v) {
    return *reinterpret_cast<uint32_t*>(&v);
}
__device__ __forceinline__ void mma_f16(float* c, const uint32_t* a, uint32_t b0, uint32_t b1) {
    asm volatile(
        "mma.sync.aligned.m16n8k16.row.col.f32.f16.f16.f32 "
        "{%0,%1,%2,%3}, {%4,%5,%6,%7}, {%8,%9}, {%0,%1,%2,%3};\n"
        : "+f"(c[0]), "+f"(c[1]), "+f"(c[2]), "+f"(c[3])
        : "r"(a[0]), "r"(a[1]), "r"(a[2]), "r"(a[3]), "r"(b0), "r"(b1));
}
__device__ __forceinline__ void ldsm_x4(uint32_t addr, uint32_t& r0, uint32_t& r1,
                                        uint32_t& r2, uint32_t& r3) {
    asm volatile("ldmatrix.sync.aligned.m8n8.x4.shared.b16 {%0,%1,%2,%3}, [%4];"
                 : "=r"(r0), "=r"(r1), "=r"(r2), "=r"(r3) : "r"(addr));
}
__device__ __forceinline__ void cp16(uint32_t smem_addr, const void* gptr) {
    asm volatile("cp.async.cg.shared.global [%0], [%1], 16;"
                 :: "r"(smem_addr), "l"(gptr));
}
#define CP_COMMIT() asm volatile("cp.async.commit_group;" ::: "memory")
#define CP_WAIT(N)  asm volatile("cp.async.wait_group %0;" :: "n"(N) : "memory")

// ---------------------------------------------------------------------------
// Prep 1: RoPE. Q -> g_qr (fp32, scaled). New K -> g_kh[h][SPLIT+s].
// ---------------------------------------------------------------------------
__global__ void rope_prep(const float* __restrict__ q, const float* __restrict__ k,
                          const float* __restrict__ fc, const float* __restrict__ fs) {
    const float SC = 1.4426950408889634f * 0.125f;
    int idx = blockIdx.x * blockDim.x + threadIdx.x;
    if (idx >= S * H * 32) return;
    int p = idx & 31;
    int h = (idx >> 5) & 15;
    int s = idx >> 9;
    int pos = START_FRAME + s;
    float c  = fc[pos * 64 + 2 * p];
    float sn = fs[pos * 64 + 2 * p];
    int base = (s * H + h) * D + 2 * p;
    float q1 = q[base], q2 = q[base + 1];
    g_qr[base]     = (q1 * c - q2 * sn) * SC;
    g_qr[base + 1] = (q2 * c + q1 * sn) * SC;
    float k1 = k[base], k2 = k[base + 1];
    *(__half2*)&g_kh[((size_t)h * NKV + SPLIT + s) * D + 2 * p] =
        __floats2half2_rn(k1 * c - k2 * sn, k2 * c + k1 * sn);
}

// ---------------------------------------------------------------------------
// Prep 2: cache K (rolled region) -> g_kh[h][0..SPLIT), fp16
// ---------------------------------------------------------------------------
__global__ void conv_k(const float* __restrict__ cache_k) {
    int idx = blockIdx.x * blockDim.x + threadIdx.x;
    if (idx >= SPLIT * H * 32) return;
    int p = idx & 31;
    int h = (idx >> 5) & 15;
    int j = idx >> 9;
    const float* src = &cache_k[(size_t)(CACHE_OFF + j) * (H * D) + h * D + 2 * p];
    *(__half2*)&g_kh[((size_t)h * NKV + j) * D + 2 * p] = __floats2half2_rn(src[0], src[1]);
}

// ---------------------------------------------------------------------------
// Prep 3: V (merged window) transposed -> g_vt[h][d][key], fp16. grid (128, 16)
// ---------------------------------------------------------------------------
__global__ __launch_bounds__(256) void transpose_v(const float* __restrict__ v_in,
                                                   const float* __restrict__ cache_v) {
    __shared__ float t[64][65];
    int kt = blockIdx.x, h = blockIdx.y, tid = threadIdx.x;
    for (int i = tid; i < 1024; i += 256) {
        int r = i >> 4, c4 = (i & 15) << 2;
        int key = kt * 64 + r;
        const float* src = (key < SPLIT)
            ? &cache_v[(size_t)(CACHE_OFF + key) * (H * D) + h * D + c4]
            : &v_in[(size_t)(key - SPLIT) * (H * D) + h * D + c4];
        float4 x = *(const float4*)src;
        t[r][c4] = x.x; t[r][c4 + 1] = x.y; t[r][c4 + 2] = x.z; t[r][c4 + 3] = x.w;
    }
    __syncthreads();
    for (int i = tid; i < 1024; i += 256) {
        int d = i >> 4, k4 = (i & 15) << 2;
        size_t dst = (size_t)(h * 64 + d) * NKV + kt * 64 + k4;
        *(__half2*)&g_vt[dst]     = __floats2half2_rn(t[k4][d], t[k4 + 1][d]);
        *(__half2*)&g_vt[dst + 2] = __floats2half2_rn(t[k4 + 2][d], t[k4 + 3][d]);
    }
}

// ---------------------------------------------------------------------------
// Flash attention, fp16 mma.sync m16n8k16 + ldmatrix.x4, 2-stage cp.async.
// grid = (16, 16, 4) = 1024 CTAs, block = 128 (4 warps x 16 q-rows), 4 CTAs/SM.
// ---------------------------------------------------------------------------
__device__ __forceinline__ void prefetch_tile(uint32_t kbase, uint32_t vbase,
                                              int tid, int h, int kt) {
    const char* ksrc = (const char*)&g_kh[((size_t)h * NKV + (size_t)kt * BN) * D];
    #pragma unroll
    for (int g = 0; g < 4; g++) {
        int idx = tid + g * 128;
        int r = idx >> 3, c = idx & 7;
        cp16(kbase + (uint32_t)(r * KS + c * 8) * 2, ksrc + (size_t)idx * 16);
    }
    #pragma unroll
    for (int g = 0; g < 4; g++) {
        int idx = tid + g * 128;
        int d = idx >> 3, c = idx & 7;
        cp16(vbase + (uint32_t)(d * KS + c * 8) * 2,
             (const char*)&g_vt[(size_t)(h * 64 + d) * NKV + (size_t)kt * BN + c * 8]);
    }
}

__global__ __launch_bounds__(128, 4) void attn_fp16() {
    // stages: [K0 | V0 | K1 | V1], each BN*KS halves
    __shared__ __align__(16) __half smem[4 * TILE_HALVES];

    const int h     = blockIdx.y;
    const int q0    = blockIdx.x * BM;
    const int split = blockIdx.z;
    const int tid   = threadIdx.x;
    const int warp  = tid >> 5;
    const int lane  = tid & 31;
    const int gid   = lane >> 2;
    const int tig   = lane & 3;
    const int kt0   = split * TPT;

    const uint32_t sb = (uint32_t)__cvta_generic_to_shared(smem);
    const uint32_t kaddr[2] = { sb, sb + 2u * TILE_HALVES * 2u };
    const uint32_t vaddr[2] = { sb + TILE_HALVES * 2u, sb + 3u * TILE_HALVES * 2u };

    // ldmatrix per-lane byte offset within a tile:
    //   lanes 0-7: nn-even rows, dim-lo | 8-15: nn-even, dim-hi
    //   lanes 16-23: nn-odd rows, dim-lo | 24-31: nn-odd, dim-hi
    const uint32_t laneoff =
        (uint32_t)((((lane >> 4) & 1) * 8 + (lane & 7)) * KS * 2 + ((lane >> 3) & 1) * 16);

    // prologue prefetch of tile 0 (overlaps Q fragment loads)
    prefetch_tile(kaddr[0], vaddr[0], tid, h, kt0);
    CP_COMMIT();

    // ---- Q A-fragments: rows (q0+warp*16+gid, +8) ----
    uint32_t qa[4][4];
    {
        int r0 = q0 + warp * 16 + gid;
        const float* qrow0 = &g_qr[(size_t)r0 * (H * D) + h * D];
        const float* qrow1 = &g_qr[(size_t)(r0 + 8) * (H * D) + h * D];
        #pragma unroll
        for (int kk = 0; kk < 4; kk++) {
            int c = kk * 16 + 2 * tig;
            float2 x0 = *(const float2*)&qrow0[c];
            float2 x1 = *(const float2*)&qrow1[c];
            float2 x2 = *(const float2*)&qrow0[c + 8];
            float2 x3 = *(const float2*)&qrow1[c + 8];
            qa[kk][0] = h2u(__floats2half2_rn(x0.x, x0.y));
            qa[kk][1] = h2u(__floats2half2_rn(x1.x, x1.y));
            qa[kk][2] = h2u(__floats2half2_rn(x2.x, x2.y));
            qa[kk][3] = h2u(__floats2half2_rn(x3.x, x3.y));
        }
    }

    float o[8][4];
    #pragma unroll
    for (int nn = 0; nn < 8; nn++)
        o[nn][0] = o[nn][1] = o[nn][2] = o[nn][3] = 0.f;
    float L0 = 0.f, L1 = 0.f;

    for (int j = 0; j < TPT; j++) {
        const int cur = j & 1;

        CP_WAIT(0);            // tile j resident
        __syncthreads();       // visible to all warps; buf[1-cur] fully consumed (iter j-1)

        if (j + 1 < TPT) {     // prefetch j+1 overlaps compute of j
            prefetch_tile(kaddr[1 - cur], vaddr[1 - cur], tid, h, kt0 + j + 1);
            CP_COMMIT();
        }

        // ---- MMA1: S = Q * K^T (log2 domain) ----
        float sacc[8][4];
        #pragma unroll
        for (int nn = 0; nn < 8; nn++)
            sacc[nn][0] = sacc[nn][1] = sacc[nn][2] = sacc[nn][3] = 0.f;
        #pragma unroll
        for (int nnp = 0; nnp < 4; nnp++) {
            #pragma unroll
            for (int kk = 0; kk < 4; kk++) {
                uint32_t b0, b1, b2, b3;
                ldsm_x4(kaddr[cur] + laneoff + (uint32_t)(nnp * 16 * KS * 2 + kk * 32),
                        b0, b1, b2, b3);
                mma_f16(sacc[2 * nnp],     qa[kk], b0, b1);
                mma_f16(sacc[2 * nnp + 1], qa[kk], b2, b3);
            }
        }

        // ---- softmax in registers: p = 2^s; L; MMA2 A-frags ----
        uint32_t pa[4][4];
        #pragma unroll
        for (int kk = 0; kk < 4; kk++) {
            float p00 = ex2(sacc[2 * kk][0]);
            float p01 = ex2(sacc[2 * kk][1]);
            float p02 = ex2(sacc[2 * kk][2]);
            float p03 = ex2(sacc[2 * kk][3]);
            float p10 = ex2(sacc[2 * kk + 1][0]);
            float p11 = ex2(sacc[2 * kk + 1][1]);
            float p12 = ex2(sacc[2 * kk + 1][2]);
            float p13 = ex2(sacc[2 * kk + 1][3]);
            L0 += (p00 + p01) + (p10 + p11);
            L1 += (p02 + p03) + (p12 + p13);
            pa[kk][0] = h2u(__floats2half2_rn(p00, p01));
            pa[kk][1] = h2u(__floats2half2_rn(p02, p03));
            pa[kk][2] = h2u(__floats2half2_rn(p10, p11));
            pa[kk][3] = h2u(__floats2half2_rn(p12, p13));
        }

        // ---- MMA2: O += P * V ----
        #pragma unroll
        for (int nnp = 0; nnp < 4; nnp++) {
            #pragma unroll
            for (int kk = 0; kk < 4; kk++) {
                uint32_t b0, b1, b2, b3;
                ldsm_x4(vaddr[cur] + laneoff + (uint32_t)(nnp * 16 * KS * 2 + kk * 32),
                        b0, b1, b2, b3);
                mma_f16(o[2 * nnp],     pa[kk], b0, b1);
                mma_f16(o[2 * nnp + 1], pa[kk], b2, b3);
            }
        }
        // no trailing sync: next iter's top sync orders buffer reuse
    }

    // ---- epilogue ----
    L0 += __shfl_xor_sync(0xffffffffu, L0, 1);
    L0 += __shfl_xor_sync(0xffffffffu, L0, 2);
    L1 += __shfl_xor_sync(0xffffffffu, L1, 1);
    L1 += __shfl_xor_sync(0xffffffffu, L1, 2);

    int r = q0 + warp * 16 + gid;
    size_t b0 = ((size_t)split * S + r) * (H * D) + h * 64;
    size_t b1 = ((size_t)split * S + r + 8) * (H * D) + h * 64;
    #pragma unroll
    for (int nn = 0; nn < 8; nn++) {
        *(float2*)&g_po[b0 + nn * 8 + 2 * tig] = make_float2(o[nn][0], o[nn][1]);
        *(float2*)&g_po[b1 + nn * 8 + 2 * tig] = make_float2(o[nn][2], o[nn][3]);
    }
    if (tig == 0) {
        g_l[(size_t)split * (S * H) + (size_t)r * H + h]       = L0;
        g_l[(size_t)split * (S * H) + (size_t)(r + 8) * H + h] = L1;
    }
}

// ---------------------------------------------------------------------------
// Merge splits (float4): out = sum(po) / sum(l)
// ---------------------------------------------------------------------------
__global__ __launch_bounds__(256) void reduce_kernel(float* __restrict__ out) {
    int i4 = blockIdx.x * blockDim.x + threadIdx.x;
    if (i4 >= S * H * D / 4) return;
    int idx = i4 * 4;
    int h = (idx >> 6) & 15;
    int s = idx >> 10;
    int mlb = s * H + h;
    float4 num = make_float4(0.f, 0.f, 0.f, 0.f);
    float den = 0.f;
    #pragma unroll
    for (int i = 0; i < NSPLIT; i++) {
        float4 p = *(const float4*)&g_po[(size_t)i * (S * H * D) + idx];
        num.x += p.x; num.y += p.y; num.z += p.z; num.w += p.w;
        den += g_l[(size_t)i * (S * H) + mlb];
    }
    float r = 1.f / den;
    *(float4*)&out[idx] = make_float4(num.x * r, num.y * r, num.z * r, num.w * r);
}

// ---------------------------------------------------------------------------
extern "C" void kernel_launch(void* const* d_in, const int* in_sizes, int n_in,
                              void* d_out, int out_size) {
    const float* q  = (const float*)d_in[0];
    const float* k  = (const float*)d_in[1];
    const float* v  = (const float*)d_in[2];
    const float* ck = (const float*)d_in[3];
    const float* cv = (const float*)d_in[4];
    const float* fc = (const float*)d_in[5];
    const float* fs = (const float*)d_in[6];
    float* out = (float*)d_out;
    (void)in_sizes; (void)n_in; (void)out_size;

    rope_prep<<<(S * H * 32 + 255) / 256, 256>>>(q, k, fc, fs);
    conv_k<<<(SPLIT * H * 32 + 255) / 256, 256>>>(ck);
    transpose_v<<<dim3(NKV / 64, H), 256>>>(v, cv);

    dim3 grid(S / BM, H, NSPLIT);
    attn_fp16<<<grid, 128>>>();

    reduce_kernel<<<(S * H * D / 4 + 255) / 256, 256>>>(out);
}

// round 7
// speedup vs baseline: 3.1207x; 1.0612x over previous
#include <cuda_runtime.h>
#include <cuda_fp16.h>
#include <cstdint>

// Problem constants
#define H 16
#define D 64
#define S 1024
#define START_FRAME 9728
#define NKV 8192
#define CACHE_OFF 2560
#define SPLIT 7168
#define BM 128
#define BN 64
#define NSPLIT 8
#define TPT (NKV / BN / NSPLIT)   // 16 kv tiles per CTA
#define KS 72                     // smem row stride in halves (144B, conflict-free)

// smem layout (in halves)
#define Q_OFF  0                  // 128 x KS
#define K0_OFF 9216               // 64 x KS
#define V0_OFF 13824              // 72 x KS (rows 64-71: ones/zeros for L)
#define K1_OFF 19008
#define V1_OFF 23616
#define SM_HALVES 28800           // 57600 bytes

// Scratch
__device__ __align__(16) float  g_qr[S * H * D];            // roped Q, scaled log2e/8
__device__ __align__(16) __half g_kh[(size_t)H * NKV * D];  // window K fp16 [h][key][d]
__device__ __align__(16) __half g_vt[(size_t)H * D * NKV];  // window V^T fp16 [h][d][key]
__device__ __align__(16) float  g_po[NSPLIT * S * H * D];   // partial O
__device__ __align__(16) float  g_l[NSPLIT * S * H];        // partial denom

// ---------------------------------------------------------------------------
// Helpers
// ---------------------------------------------------------------------------
__device__ __forceinline__ uint32_t cvt_f16x2(float hi, float lo) {
    uint32_t r;
    asm("cvt.rn.f16x2.f32 %0, %1, %2;" : "=r"(r) : "f"(hi), "f"(lo));
    return r;
}
__device__ __forceinline__ uint32_t ex2_f16x2(uint32_t x) {
    uint32_t y;
    asm("ex2.approx.f16x2 %0, %1;" : "=r"(y) : "r"(x));
    return y;
}
__device__ __forceinline__ void mma_f16(float* c, const uint32_t* a, uint32_t b0, uint32_t b1) {
    asm volatile(
        "mma.sync.aligned.m16n8k16.row.col.f32.f16.f16.f32 "
        "{%0,%1,%2,%3}, {%4,%5,%6,%7}, {%8,%9}, {%0,%1,%2,%3};\n"
        : "+f"(c[0]), "+f"(c[1]), "+f"(c[2]), "+f"(c[3])
        : "r"(a[0]), "r"(a[1]), "r"(a[2]), "r"(a[3]), "r"(b0), "r"(b1));
}
__device__ __forceinline__ void ldsm_x4(uint32_t addr, uint32_t& r0, uint32_t& r1,
                                        uint32_t& r2, uint32_t& r3) {
    asm volatile("ldmatrix.sync.aligned.m8n8.x4.shared.b16 {%0,%1,%2,%3}, [%4];"
                 : "=r"(r0), "=r"(r1), "=r"(r2), "=r"(r3) : "r"(addr));
}
__device__ __forceinline__ void ldsm_x2(uint32_t addr, uint32_t& r0, uint32_t& r1) {
    asm volatile("ldmatrix.sync.aligned.m8n8.x2.shared.b16 {%0,%1}, [%2];"
                 : "=r"(r0), "=r"(r1) : "r"(addr));
}
__device__ __forceinline__ void cp16(uint32_t smem_addr, const void* gptr) {
    asm volatile("cp.async.cg.shared.global [%0], [%1], 16;"
                 :: "r"(smem_addr), "l"(gptr));
}
#define CP_COMMIT() asm volatile("cp.async.commit_group;" ::: "memory")
#define CP_WAIT(N)  asm volatile("cp.async.wait_group %0;" :: "n"(N) : "memory")

// ---------------------------------------------------------------------------
// Prep 1: RoPE. Q -> g_qr (fp32, scaled). New K -> g_kh[h][SPLIT+s].
// ---------------------------------------------------------------------------
__global__ void rope_prep(const float* __restrict__ q, const float* __restrict__ k,
                          const float* __restrict__ fc, const float* __restrict__ fs) {
    const float SC = 1.4426950408889634f * 0.125f;
    int idx = blockIdx.x * blockDim.x + threadIdx.x;
    if (idx >= S * H * 32) return;
    int p = idx & 31;
    int h = (idx >> 5) & 15;
    int s = idx >> 9;
    int pos = START_FRAME + s;
    float c  = fc[pos * 64 + 2 * p];
    float sn = fs[pos * 64 + 2 * p];
    int base = (s * H + h) * D + 2 * p;
    float q1 = q[base], q2 = q[base + 1];
    g_qr[base]     = (q1 * c - q2 * sn) * SC;
    g_qr[base + 1] = (q2 * c + q1 * sn) * SC;
    float k1 = k[base], k2 = k[base + 1];
    *(__half2*)&g_kh[((size_t)h * NKV + SPLIT + s) * D + 2 * p] =
        __floats2half2_rn(k1 * c - k2 * sn, k2 * c + k1 * sn);
}

// ---------------------------------------------------------------------------
// Prep 2: cache K (rolled region) -> g_kh[h][0..SPLIT), fp16
// ---------------------------------------------------------------------------
__global__ void conv_k(const float* __restrict__ cache_k) {
    int idx = blockIdx.x * blockDim.x + threadIdx.x;
    if (idx >= SPLIT * H * 32) return;
    int p = idx & 31;
    int h = (idx >> 5) & 15;
    int j = idx >> 9;
    const float* src = &cache_k[(size_t)(CACHE_OFF + j) * (H * D) + h * D + 2 * p];
    *(__half2*)&g_kh[((size_t)h * NKV + j) * D + 2 * p] = __floats2half2_rn(src[0], src[1]);
}

// ---------------------------------------------------------------------------
// Prep 3: V (merged window) transposed -> g_vt[h][d][key], fp16. grid (128, 16)
// ---------------------------------------------------------------------------
__global__ __launch_bounds__(256) void transpose_v(const float* __restrict__ v_in,
                                                   const float* __restrict__ cache_v) {
    __shared__ float t[64][65];
    int kt = blockIdx.x, h = blockIdx.y, tid = threadIdx.x;
    for (int i = tid; i < 1024; i += 256) {
        int r = i >> 4, c4 = (i & 15) << 2;
        int key = kt * 64 + r;
        const float* src = (key < SPLIT)
            ? &cache_v[(size_t)(CACHE_OFF + key) * (H * D) + h * D + c4]
            : &v_in[(size_t)(key - SPLIT) * (H * D) + h * D + c4];
        float4 x = *(const float4*)src;
        t[r][c4] = x.x; t[r][c4 + 1] = x.y; t[r][c4 + 2] = x.z; t[r][c4 + 3] = x.w;
    }
    __syncthreads();
    for (int i = tid; i < 1024; i += 256) {
        int d = i >> 4, k4 = (i & 15) << 2;
        size_t dst = (size_t)(h * 64 + d) * NKV + kt * 64 + k4;
        *(__half2*)&g_vt[dst]     = __floats2half2_rn(t[k4][d], t[k4 + 1][d]);
        *(__half2*)&g_vt[dst + 2] = __floats2half2_rn(t[k4 + 2][d], t[k4 + 3][d]);
    }
}

// ---------------------------------------------------------------------------
// Flash attention: fp16 mma m16n8k16, ldmatrix A+B, 2-stage cp.async,
// L computed exactly via ones-row MMA, f16x2 softmax.
// grid = (8, 16, 8) = 1024 CTAs, block = 128 (4 warps x 32 q-rows), 3 CTAs/SM.
// ---------------------------------------------------------------------------
__device__ __forceinline__ void prefetch_tile(uint32_t kbase, uint32_t vbase,
                                              int tid, int h, int kt) {
    const char* ksrc = (const char*)&g_kh[((size_t)h * NKV + (size_t)kt * BN) * D];
    #pragma unroll
    for (int g = 0; g < 4; g++) {
        int idx = tid + g * 128;
        int r = idx >> 3, c = idx & 7;
        cp16(kbase + (uint32_t)(r * KS + c * 8) * 2, ksrc + (size_t)idx * 16);
    }
    #pragma unroll
    for (int g = 0; g < 4; g++) {
        int idx = tid + g * 128;
        int d = idx >> 3, c = idx & 7;
        cp16(vbase + (uint32_t)(d * KS + c * 8) * 2,
             (const char*)&g_vt[(size_t)(h * 64 + d) * NKV + (size_t)kt * BN + c * 8]);
    }
}

__global__ __launch_bounds__(128, 3) void attn_fp16() {
    extern __shared__ __align__(16) __half smem[];

    const int h     = blockIdx.y;
    const int q0    = blockIdx.x * BM;
    const int split = blockIdx.z;
    const int tid   = threadIdx.x;
    const int warp  = tid >> 5;
    const int lane  = tid & 31;
    const int gid   = lane >> 2;
    const int tig   = lane & 3;
    const int kt0   = split * TPT;

    const uint32_t sb = (uint32_t)__cvta_generic_to_shared(smem);
    const uint32_t qbase    = sb + Q_OFF * 2u;
    const uint32_t kaddr[2] = { sb + K0_OFF * 2u, sb + K1_OFF * 2u };
    const uint32_t vaddr[2] = { sb + V0_OFF * 2u, sb + V1_OFF * 2u };

    // B-fragment ldsm lane offset (validated in round 6)
    const uint32_t loffB =
        (uint32_t)((((lane >> 4) & 1) * 8 + (lane & 7)) * KS * 2 + ((lane >> 3) & 1) * 16);
    // A-fragment ldsm lane offset: lanes 0-15 rows 0-15 (k-lo), 16-31 same rows (k-hi)
    const uint32_t loffA =
        (uint32_t)((lane & 15) * KS * 2 + ((lane >> 4) & 1) * 16);
    // ones-row (L) ldsm_x2 lane offset: rows 64-71, lo/hi 8-cols
    const uint32_t loffL =
        (uint32_t)((64 + (lane & 7)) * KS * 2 + ((lane >> 3) & 1) * 16);

    // prologue prefetch of tile 0
    prefetch_tile(kaddr[0], vaddr[0], tid, h, kt0);
    CP_COMMIT();

    // stage Q (fp32 -> fp16) into smem rows 0..127
    {
        const float* qsrc = &g_qr[(size_t)q0 * (H * D) + h * D];
        #pragma unroll
        for (int g = 0; g < 8; g++) {
            int i = tid + g * 128;
            int r = i >> 3, c8 = (i & 7) * 8;
            float4 a = *(const float4*)&qsrc[(size_t)r * (H * D) + c8];
            float4 b = *(const float4*)&qsrc[(size_t)r * (H * D) + c8 + 4];
            uint32_t u0 = cvt_f16x2(a.y, a.x);
            uint32_t u1 = cvt_f16x2(a.w, a.z);
            uint32_t u2 = cvt_f16x2(b.y, b.x);
            uint32_t u3 = cvt_f16x2(b.w, b.z);
            *(uint4*)&smem[Q_OFF + r * KS + c8] = make_uint4(u0, u1, u2, u3);
        }
    }
    // init ones/zeros rows 64-71 of both V buffers (never overwritten by cp.async)
    {
        const __half one = __float2half(1.0f), zero = __float2half(0.0f);
        for (int i = tid; i < 512; i += 128) {
            int r = 64 + (i >> 6), c = i & 63;
            __half val = (r == 64) ? one : zero;
            smem[V0_OFF + r * KS + c] = val;
            smem[V1_OFF + r * KS + c] = val;
        }
    }

    float o[2][8][4];
    #pragma unroll
    for (int mt = 0; mt < 2; mt++)
        #pragma unroll
        for (int nn = 0; nn < 8; nn++)
            o[mt][nn][0] = o[mt][nn][1] = o[mt][nn][2] = o[mt][nn][3] = 0.f;
    float oL[2][4];
    #pragma unroll
    for (int mt = 0; mt < 2; mt++)
        oL[mt][0] = oL[mt][1] = oL[mt][2] = oL[mt][3] = 0.f;

    for (int j = 0; j < TPT; j++) {
        const int cur = j & 1;

        CP_WAIT(0);
        __syncthreads();       // tile j visible; buf[1-cur] consumed (iter j-1)

        if (j + 1 < TPT) {
            prefetch_tile(kaddr[1 - cur], vaddr[1 - cur], tid, h, kt0 + j + 1);
            CP_COMMIT();
        }

        // ---- Q A-fragments for this warp (from smem, per tile) ----
        uint32_t qa[2][4][4];
        #pragma unroll
        for (int mt = 0; mt < 2; mt++) {
            uint32_t rowbase = qbase + (uint32_t)((warp * 32 + mt * 16) * KS * 2) + loffA;
            #pragma unroll
            for (int kk = 0; kk < 4; kk++)
                ldsm_x4(rowbase + (uint32_t)(kk * 32),
                        qa[mt][kk][0], qa[mt][kk][1], qa[mt][kk][2], qa[mt][kk][3]);
        }

        // ---- MMA1 + per-nnp softmax -> pa ----
        uint32_t pa[2][4][4];
        #pragma unroll
        for (int nnp = 0; nnp < 4; nnp++) {
            float sacc[2][2][4];
            #pragma unroll
            for (int mt = 0; mt < 2; mt++)
                #pragma unroll
                for (int nn = 0; nn < 2; nn++)
                    sacc[mt][nn][0] = sacc[mt][nn][1] = sacc[mt][nn][2] = sacc[mt][nn][3] = 0.f;
            #pragma unroll
            for (int kk = 0; kk < 4; kk++) {
                uint32_t b0, b1, b2, b3;
                ldsm_x4(kaddr[cur] + loffB + (uint32_t)(nnp * 16 * KS * 2 + kk * 32),
                        b0, b1, b2, b3);
                mma_f16(sacc[0][0], qa[0][kk], b0, b1);
                mma_f16(sacc[0][1], qa[0][kk], b2, b3);
                mma_f16(sacc[1][0], qa[1][kk], b0, b1);
                mma_f16(sacc[1][1], qa[1][kk], b2, b3);
            }
            #pragma unroll
            for (int mt = 0; mt < 2; mt++) {
                pa[mt][nnp][0] = ex2_f16x2(cvt_f16x2(sacc[mt][0][1], sacc[mt][0][0]));
                pa[mt][nnp][1] = ex2_f16x2(cvt_f16x2(sacc[mt][0][3], sacc[mt][0][2]));
                pa[mt][nnp][2] = ex2_f16x2(cvt_f16x2(sacc[mt][1][1], sacc[mt][1][0]));
                pa[mt][nnp][3] = ex2_f16x2(cvt_f16x2(sacc[mt][1][3], sacc[mt][1][2]));
            }
        }

        // ---- MMA2: O += P * V ----
        #pragma unroll
        for (int nnp = 0; nnp < 4; nnp++) {
            #pragma unroll
            for (int kk = 0; kk < 4; kk++) {
                uint32_t b0, b1, b2, b3;
                ldsm_x4(vaddr[cur] + loffB + (uint32_t)(nnp * 16 * KS * 2 + kk * 32),
                        b0, b1, b2, b3);
                mma_f16(o[0][2 * nnp],     pa[0][kk], b0, b1);
                mma_f16(o[0][2 * nnp + 1], pa[0][kk], b2, b3);
                mma_f16(o[1][2 * nnp],     pa[1][kk], b0, b1);
                mma_f16(o[1][2 * nnp + 1], pa[1][kk], b2, b3);
            }
        }
        // ---- L: extra n-tile vs ones-row (exact fp32 accumulation) ----
        #pragma unroll
        for (int kk = 0; kk < 4; kk++) {
            uint32_t bL0, bL1;
            ldsm_x2(vaddr[cur] + loffL + (uint32_t)(kk * 32), bL0, bL1);
            mma_f16(oL[0], pa[0][kk], bL0, bL1);
            mma_f16(oL[1], pa[1][kk], bL0, bL1);
        }
        // next iter's top sync orders buffer reuse
    }

    // ---- epilogue ----
    #pragma unroll
    for (int mt = 0; mt < 2; mt++) {
        int r = q0 + warp * 32 + mt * 16 + gid;
        size_t b0 = ((size_t)split * S + r) * (H * D) + h * 64;
        size_t b1 = ((size_t)split * S + r + 8) * (H * D) + h * 64;
        #pragma unroll
        for (int nn = 0; nn < 8; nn++) {
            *(float2*)&g_po[b0 + nn * 8 + 2 * tig] = make_float2(o[mt][nn][0], o[mt][nn][1]);
            *(float2*)&g_po[b1 + nn * 8 + 2 * tig] = make_float2(o[mt][nn][2], o[mt][nn][3]);
        }
        if (tig == 0) {   // col 64 of the ones-tile = exact L
            g_l[(size_t)split * (S * H) + (size_t)r * H + h]       = oL[mt][0];
            g_l[(size_t)split * (S * H) + (size_t)(r + 8) * H + h] = oL[mt][2];
        }
    }
}

// ---------------------------------------------------------------------------
// Merge splits (float4): out = sum(po) / sum(l)
// ---------------------------------------------------------------------------
__global__ __launch_bounds__(256) void reduce_kernel(float* __restrict__ out) {
    int i4 = blockIdx.x * blockDim.x + threadIdx.x;
    if (i4 >= S * H * D / 4) return;
    int idx = i4 * 4;
    int h = (idx >> 6) & 15;
    int s = idx >> 10;
    int mlb = s * H + h;
    float4 num = make_float4(0.f, 0.f, 0.f, 0.f);
    float den = 0.f;
    #pragma unroll
    for (int i = 0; i < NSPLIT; i++) {
        float4 p = *(const float4*)&g_po[(size_t)i * (S * H * D) + idx];
        num.x += p.x; num.y += p.y; num.z += p.z; num.w += p.w;
        den += g_l[(size_t)i * (S * H) + mlb];
    }
    float r = 1.f / den;
    *(float4*)&out[idx] = make_float4(num.x * r, num.y * r, num.z * r, num.w * r);
}

// ---------------------------------------------------------------------------
extern "C" void kernel_launch(void* const* d_in, const int* in_sizes, int n_in,
                              void* d_out, int out_size) {
    const float* q  = (const float*)d_in[0];
    const float* k  = (const float*)d_in[1];
    const float* v  = (const float*)d_in[2];
    const float* ck = (const float*)d_in[3];
    const float* cv = (const float*)d_in[4];
    const float* fc = (const float*)d_in[5];
    const float* fs = (const float*)d_in[6];
    float* out = (float*)d_out;
    (void)in_sizes; (void)n_in; (void)out_size;

    rope_prep<<<(S * H * 32 + 255) / 256, 256>>>(q, k, fc, fs);
    conv_k<<<(SPLIT * H * 32 + 255) / 256, 256>>>(ck);
    transpose_v<<<dim3(NKV / 64, H), 256>>>(v, cv);

    cudaFuncSetAttribute(attn_fp16, cudaFuncAttributeMaxDynamicSharedMemorySize,
                         SM_HALVES * 2);
    dim3 grid(S / BM, H, NSPLIT);
    attn_fp16<<<grid, 128, SM_HALVES * 2>>>();

    reduce_kernel<<<(S * H * D / 4 + 255) / 256, 256>>>(out);
}

// round 8
// speedup vs baseline: 3.3368x; 1.0692x over previous
#include <cuda_runtime.h>
#include <cuda_fp16.h>
#include <cstdint>

// Problem constants
#define H 16
#define D 64
#define S 1024
#define START_FRAME 9728
#define NKV 8192
#define CACHE_OFF 2560
#define SPLIT 7168
#define BM 128
#define BN 64
#define NSPLIT 8
#define TPT (NKV / BN / NSPLIT)   // 16 kv tiles per CTA
#define KS 72                     // smem row stride in halves (144B, conflict-free)

// smem layout (halves): Q [128][72]; 3 stages of (K [64][72], V [64][72])
#define Q_OFF     0
#define TILE_H    4608            // 64*72
#define STAGE_H   (2 * TILE_H)
#define KOFF(t)   (9216 + (t) * STAGE_H)
#define VOFF(t)   (9216 + (t) * STAGE_H + TILE_H)
#define SM_HALVES (9216 + 3 * STAGE_H)   // 36864 halves = 73728 B

// Scratch
__device__ __align__(16) float  g_qr[S * H * D];            // roped Q, scaled log2e/8
__device__ __align__(16) __half g_kh[(size_t)H * NKV * D];  // window K fp16 [h][key][d]
__device__ __align__(16) __half g_vh[(size_t)H * NKV * D];  // window V fp16 [h][key][d]
__device__ __align__(16) float  g_po[NSPLIT * S * H * D];   // partial O
__device__ __align__(16) float  g_l[NSPLIT * S * H];        // partial denom

// ---------------------------------------------------------------------------
// Helpers
// ---------------------------------------------------------------------------
__device__ __forceinline__ uint32_t cvt_f16x2(float hi, float lo) {
    uint32_t r;
    asm("cvt.rn.f16x2.f32 %0, %1, %2;" : "=r"(r) : "f"(hi), "f"(lo));
    return r;
}
__device__ __forceinline__ uint32_t ex2_f16x2(uint32_t x) {
    uint32_t y;
    asm("ex2.approx.f16x2 %0, %1;" : "=r"(y) : "r"(x));
    return y;
}
__device__ __forceinline__ void mma_f16(float* c, const uint32_t* a, uint32_t b0, uint32_t b1) {
    asm volatile(
        "mma.sync.aligned.m16n8k16.row.col.f32.f16.f16.f32 "
        "{%0,%1,%2,%3}, {%4,%5,%6,%7}, {%8,%9}, {%0,%1,%2,%3};\n"
        : "+f"(c[0]), "+f"(c[1]), "+f"(c[2]), "+f"(c[3])
        : "r"(a[0]), "r"(a[1]), "r"(a[2]), "r"(a[3]), "r"(b0), "r"(b1));
}
__device__ __forceinline__ void ldsm_x4(uint32_t addr, uint32_t& r0, uint32_t& r1,
                                        uint32_t& r2, uint32_t& r3) {
    asm volatile("ldmatrix.sync.aligned.m8n8.x4.shared.b16 {%0,%1,%2,%3}, [%4];"
                 : "=r"(r0), "=r"(r1), "=r"(r2), "=r"(r3) : "r"(addr));
}
__device__ __forceinline__ void ldsm_x4_t(uint32_t addr, uint32_t& r0, uint32_t& r1,
                                          uint32_t& r2, uint32_t& r3) {
    asm volatile("ldmatrix.sync.aligned.m8n8.x4.trans.shared.b16 {%0,%1,%2,%3}, [%4];"
                 : "=r"(r0), "=r"(r1), "=r"(r2), "=r"(r3) : "r"(addr));
}
__device__ __forceinline__ void ldsm_x2_t(uint32_t addr, uint32_t& r0, uint32_t& r1) {
    asm volatile("ldmatrix.sync.aligned.m8n8.x2.trans.shared.b16 {%0,%1}, [%2];"
                 : "=r"(r0), "=r"(r1) : "r"(addr));
}
__device__ __forceinline__ void cp16(uint32_t smem_addr, const void* gptr) {
    asm volatile("cp.async.cg.shared.global [%0], [%1], 16;"
                 :: "r"(smem_addr), "l"(gptr));
}
#define CP_COMMIT() asm volatile("cp.async.commit_group;" ::: "memory")
#define CP_WAIT(N)  asm volatile("cp.async.wait_group %0;" :: "n"(N) : "memory")

// ---------------------------------------------------------------------------
// Prep 1: RoPE. Q -> g_qr (fp32, scaled). New K/V -> g_kh/g_vh[h][SPLIT+s].
// ---------------------------------------------------------------------------
__global__ void rope_prep(const float* __restrict__ q, const float* __restrict__ k,
                          const float* __restrict__ v,
                          const float* __restrict__ fc, const float* __restrict__ fs) {
    const float SC = 1.4426950408889634f * 0.125f;
    int idx = blockIdx.x * blockDim.x + threadIdx.x;
    if (idx >= S * H * 32) return;
    int p = idx & 31;
    int h = (idx >> 5) & 15;
    int s = idx >> 9;
    int pos = START_FRAME + s;
    float c  = fc[pos * 64 + 2 * p];
    float sn = fs[pos * 64 + 2 * p];
    int base = (s * H + h) * D + 2 * p;
    float q1 = q[base], q2 = q[base + 1];
    g_qr[base]     = (q1 * c - q2 * sn) * SC;
    g_qr[base + 1] = (q2 * c + q1 * sn) * SC;
    float k1 = k[base], k2 = k[base + 1];
    size_t dst = ((size_t)h * NKV + SPLIT + s) * D + 2 * p;
    *(uint32_t*)&g_kh[dst] = cvt_f16x2(k2 * c + k1 * sn, k1 * c - k2 * sn);
    float2 vv = *(const float2*)&v[base];
    *(uint32_t*)&g_vh[dst] = cvt_f16x2(vv.y, vv.x);
}

// ---------------------------------------------------------------------------
// Prep 2: cache K,V (rolled region) -> g_kh/g_vh[h][0..SPLIT), fp16
// ---------------------------------------------------------------------------
__global__ void conv_kv(const float* __restrict__ cache_k,
                        const float* __restrict__ cache_v) {
    int i4 = blockIdx.x * blockDim.x + threadIdx.x;   // SPLIT*H*16
    if (i4 >= SPLIT * H * 16) return;
    int c4 = (i4 & 15) << 2;
    int h  = (i4 >> 4) & 15;
    int j  = i4 >> 8;
    size_t src = (size_t)(CACHE_OFF + j) * (H * D) + h * D + c4;
    float4 kk = *(const float4*)&cache_k[src];
    float4 vv = *(const float4*)&cache_v[src];
    size_t dst = ((size_t)h * NKV + j) * D + c4;
    *(uint2*)&g_kh[dst] = make_uint2(cvt_f16x2(kk.y, kk.x), cvt_f16x2(kk.w, kk.z));
    *(uint2*)&g_vh[dst] = make_uint2(cvt_f16x2(vv.y, vv.x), cvt_f16x2(vv.w, vv.z));
}

// ---------------------------------------------------------------------------
// Flash attention: fp16 mma m16n8k16, ldmatrix A/B (+.trans for V), 3-stage
// cp.async, L via ones-column MMA, f16x2 softmax.
// grid = (8, 16, 8) = 1024 CTAs, block = 128 (4 warps x 32 q-rows), 3 CTAs/SM.
// ---------------------------------------------------------------------------
__device__ __forceinline__ void prefetch_tile(uint32_t kbase, uint32_t vbase,
                                              int tid, int h, int kt) {
    const char* ksrc = (const char*)&g_kh[((size_t)h * NKV + (size_t)kt * BN) * D];
    const char* vsrc = (const char*)&g_vh[((size_t)h * NKV + (size_t)kt * BN) * D];
    #pragma unroll
    for (int g = 0; g < 4; g++) {
        int idx = tid + g * 128;
        int r = idx >> 3, c = idx & 7;
        uint32_t off = (uint32_t)(r * KS + c * 8) * 2;
        cp16(kbase + off, ksrc + (size_t)idx * 16);
        cp16(vbase + off, vsrc + (size_t)idx * 16);
    }
}

__global__ __launch_bounds__(128, 3) void attn_fp16() {
    extern __shared__ __align__(16) __half smem[];

    const int h     = blockIdx.y;
    const int q0    = blockIdx.x * BM;
    const int split = blockIdx.z;
    const int tid   = threadIdx.x;
    const int warp  = tid >> 5;
    const int lane  = tid & 31;
    const int gid   = lane >> 2;
    const int tig   = lane & 3;
    const int kt0   = split * TPT;

    const uint32_t sb = (uint32_t)__cvta_generic_to_shared(smem);
    const uint32_t qbase = sb + Q_OFF * 2u;
    uint32_t kaddr[3], vaddr[3];
    #pragma unroll
    for (int t = 0; t < 3; t++) {
        kaddr[t] = sb + KOFF(t) * 2u;
        vaddr[t] = sb + VOFF(t) * 2u;
    }

    // K (non-trans B): bit4 -> +8 rows(n), bit3 -> +16B (k-octet)
    const uint32_t loffB =
        (uint32_t)((((lane >> 4) & 1) * 8 + (lane & 7)) * KS * 2 + ((lane >> 3) & 1) * 16);
    // Q (A-frag): lanes 0-15 rows 0-15 (k-lo 16B), 16-31 same rows k-hi
    const uint32_t loffA =
        (uint32_t)((lane & 15) * KS * 2 + ((lane >> 4) & 1) * 16);
    // V (.trans B from [key][dim]): bit3 -> +8 keys, bit4 -> +16B (dim-octet)
    const uint32_t loffBV =
        (uint32_t)((((lane >> 3) & 1) * 8 + (lane & 7)) * KS * 2 + ((lane >> 4) & 1) * 16);
    // L ones-column (.trans x2): keys via bit3, dims 64-71 (byte 128)
    const uint32_t loffLV =
        (uint32_t)((((lane >> 3) & 1) * 8 + (lane & 7)) * KS * 2 + 128);

    // prologue: prefetch tiles 0,1
    prefetch_tile(kaddr[0], vaddr[0], tid, h, kt0);
    CP_COMMIT();
    prefetch_tile(kaddr[1], vaddr[1], tid, h, kt0 + 1);
    CP_COMMIT();

    // stage Q (fp32 -> fp16) rows 0..127
    {
        const float* qsrc = &g_qr[(size_t)q0 * (H * D) + h * D];
        #pragma unroll
        for (int g = 0; g < 8; g++) {
            int i = tid + g * 128;
            int r = i >> 3, c8 = (i & 7) * 8;
            float4 a = *(const float4*)&qsrc[(size_t)r * (H * D) + c8];
            float4 b = *(const float4*)&qsrc[(size_t)r * (H * D) + c8 + 4];
            *(uint4*)&smem[Q_OFF + r * KS + c8] = make_uint4(
                cvt_f16x2(a.y, a.x), cvt_f16x2(a.w, a.z),
                cvt_f16x2(b.y, b.x), cvt_f16x2(b.w, b.z));
        }
    }
    // ones-column (dim 64) / zeros (65-71) in all 3 V buffers
    {
        const __half one = __float2half(1.0f), zero = __float2half(0.0f);
        for (int i = tid; i < 3 * 64 * 8; i += 128) {
            int t = i >> 9, rem = i & 511;
            int key = rem >> 3, dd = 64 + (rem & 7);
            smem[VOFF(t) + key * KS + dd] = (dd == 64) ? one : zero;
        }
    }

    float o[2][8][4];
    #pragma unroll
    for (int mt = 0; mt < 2; mt++)
        #pragma unroll
        for (int nn = 0; nn < 8; nn++)
            o[mt][nn][0] = o[mt][nn][1] = o[mt][nn][2] = o[mt][nn][3] = 0.f;
    float oL[2][4];
    #pragma unroll
    for (int mt = 0; mt < 2; mt++)
        oL[mt][0] = oL[mt][1] = oL[mt][2] = oL[mt][3] = 0.f;

    for (int j = 0; j < TPT; j++) {
        const int cur = j % 3;

        if (j + 1 < TPT) { CP_WAIT(1); } else { CP_WAIT(0); }
        __syncthreads();      // tile j visible; buf[(j+2)%3] fully consumed (iter j-1)

        if (j + 2 < TPT) {
            prefetch_tile(kaddr[(j + 2) % 3], vaddr[(j + 2) % 3], tid, h, kt0 + j + 2);
            CP_COMMIT();
        }

        // ---- Q A-fragments for this warp ----
        uint32_t qa[2][4][4];
        #pragma unroll
        for (int mt = 0; mt < 2; mt++) {
            uint32_t rowbase = qbase + (uint32_t)((warp * 32 + mt * 16) * KS * 2) + loffA;
            #pragma unroll
            for (int kk = 0; kk < 4; kk++)
                ldsm_x4(rowbase + (uint32_t)(kk * 32),
                        qa[mt][kk][0], qa[mt][kk][1], qa[mt][kk][2], qa[mt][kk][3]);
        }

        // ---- MMA1 + per-nnp softmax -> pa  (nnp = key-block of 16) ----
        uint32_t pa[2][4][4];
        #pragma unroll
        for (int nnp = 0; nnp < 4; nnp++) {
            float sacc[2][2][4];
            #pragma unroll
            for (int mt = 0; mt < 2; mt++)
                #pragma unroll
                for (int nn = 0; nn < 2; nn++)
                    sacc[mt][nn][0] = sacc[mt][nn][1] = sacc[mt][nn][2] = sacc[mt][nn][3] = 0.f;
            #pragma unroll
            for (int kk = 0; kk < 4; kk++) {
                uint32_t b0, b1, b2, b3;
                ldsm_x4(kaddr[cur] + loffB + (uint32_t)(nnp * 16 * KS * 2 + kk * 32),
                        b0, b1, b2, b3);
                mma_f16(sacc[0][0], qa[0][kk], b0, b1);
                mma_f16(sacc[0][1], qa[0][kk], b2, b3);
                mma_f16(sacc[1][0], qa[1][kk], b0, b1);
                mma_f16(sacc[1][1], qa[1][kk], b2, b3);
            }
            #pragma unroll
            for (int mt = 0; mt < 2; mt++) {
                pa[mt][nnp][0] = ex2_f16x2(cvt_f16x2(sacc[mt][0][1], sacc[mt][0][0]));
                pa[mt][nnp][1] = ex2_f16x2(cvt_f16x2(sacc[mt][0][3], sacc[mt][0][2]));
                pa[mt][nnp][2] = ex2_f16x2(cvt_f16x2(sacc[mt][1][1], sacc[mt][1][0]));
                pa[mt][nnp][3] = ex2_f16x2(cvt_f16x2(sacc[mt][1][3], sacc[mt][1][2]));
            }
        }

        // ---- MMA2: O += P * V  (V [key][dim] via .trans; nnp = dim-block) ----
        #pragma unroll
        for (int nnp = 0; nnp < 4; nnp++) {
            #pragma unroll
            for (int kk = 0; kk < 4; kk++) {
                uint32_t b0, b1, b2, b3;
                ldsm_x4_t(vaddr[cur] + loffBV + (uint32_t)(kk * 16 * KS * 2 + nnp * 32),
                          b0, b1, b2, b3);
                mma_f16(o[0][2 * nnp],     pa[0][kk], b0, b1);
                mma_f16(o[0][2 * nnp + 1], pa[0][kk], b2, b3);
                mma_f16(o[1][2 * nnp],     pa[1][kk], b0, b1);
                mma_f16(o[1][2 * nnp + 1], pa[1][kk], b2, b3);
            }
        }
        // ---- L: ones-column tile (exact fp32 accumulation) ----
        #pragma unroll
        for (int kk = 0; kk < 4; kk++) {
            uint32_t bL0, bL1;
            ldsm_x2_t(vaddr[cur] + loffLV + (uint32_t)(kk * 16 * KS * 2), bL0, bL1);
            mma_f16(oL[0], pa[0][kk], bL0, bL1);
            mma_f16(oL[1], pa[1][kk], bL0, bL1);
        }
    }

    // ---- epilogue ----
    #pragma unroll
    for (int mt = 0; mt < 2; mt++) {
        int r = q0 + warp * 32 + mt * 16 + gid;
        size_t b0 = ((size_t)split * S + r) * (H * D) + h * 64;
        size_t b1 = ((size_t)split * S + r + 8) * (H * D) + h * 64;
        #pragma unroll
        for (int nn = 0; nn < 8; nn++) {
            *(float2*)&g_po[b0 + nn * 8 + 2 * tig] = make_float2(o[mt][nn][0], o[mt][nn][1]);
            *(float2*)&g_po[b1 + nn * 8 + 2 * tig] = make_float2(o[mt][nn][2], o[mt][nn][3]);
        }
        if (tig == 0) {
            g_l[(size_t)split * (S * H) + (size_t)r * H + h]       = oL[mt][0];
            g_l[(size_t)split * (S * H) + (size_t)(r + 8) * H + h] = oL[mt][2];
        }
    }
}

// ---------------------------------------------------------------------------
// Merge splits (float4): out = sum(po) / sum(l)
// ---------------------------------------------------------------------------
__global__ __launch_bounds__(256) void reduce_kernel(float* __restrict__ out) {
    int i4 = blockIdx.x * blockDim.x + threadIdx.x;
    if (i4 >= S * H * D / 4) return;
    int idx = i4 * 4;
    int h = (idx >> 6) & 15;
    int s = idx >> 10;
    int mlb = s * H + h;
    float4 num = make_float4(0.f, 0.f, 0.f, 0.f);
    float den = 0.f;
    #pragma unroll
    for (int i = 0; i < NSPLIT; i++) {
        float4 p = *(const float4*)&g_po[(size_t)i * (S * H * D) + idx];
        num.x += p.x; num.y += p.y; num.z += p.z; num.w += p.w;
        den += g_l[(size_t)i * (S * H) + mlb];
    }
    float r = 1.f / den;
    *(float4*)&out[idx] = make_float4(num.x * r, num.y * r, num.z * r, num.w * r);
}

// ---------------------------------------------------------------------------
extern "C" void kernel_launch(void* const* d_in, const int* in_sizes, int n_in,
                              void* d_out, int out_size) {
    const float* q  = (const float*)d_in[0];
    const float* k  = (const float*)d_in[1];
    const float* v  = (const float*)d_in[2];
    const float* ck = (const float*)d_in[3];
    const float* cv = (const float*)d_in[4];
    const float* fc = (const float*)d_in[5];
    const float* fs = (const float*)d_in[6];
    float* out = (float*)d_out;
    (void)in_sizes; (void)n_in; (void)out_size;

    rope_prep<<<(S * H * 32 + 255) / 256, 256>>>(q, k, v, fc, fs);
    conv_kv<<<(SPLIT * H * 16 + 255) / 256, 256>>>(ck, cv);

    cudaFuncSetAttribute(attn_fp16, cudaFuncAttributeMaxDynamicSharedMemorySize,
                         SM_HALVES * 2);
    dim3 grid(S / BM, H, NSPLIT);
    attn_fp16<<<grid, 128, SM_HALVES * 2>>>();

    reduce_kernel<<<(S * H * D / 4 + 255) / 256, 256>>>(out);
}

// round 9
// speedup vs baseline: 3.3951x; 1.0175x over previous
#include <cuda_runtime.h>
#include <cuda_fp16.h>
#include <cstdint>

// Problem constants
#define H 16
#define D 64
#define S 1024
#define START_FRAME 9728
#define NKV 8192
#define CACHE_OFF 2560
#define SPLIT 7168
#define BM 128
#define BN 64
#define NSPLIT 8
#define TPT (NKV / BN / NSPLIT)   // 16 kv tiles per CTA
#define KS 72                     // smem row stride in halves (144B, conflict-free)

// smem layout (halves): Q [128][72]; 3 stages of (K [64][72], V [64][72])
#define Q_OFF     0
#define TILE_H    4608            // 64*72
#define STAGE_H   (2 * TILE_H)
#define KOFF(t)   (9216 + (t) * STAGE_H)
#define VOFF(t)   (9216 + (t) * STAGE_H + TILE_H)
#define SM_HALVES (9216 + 3 * STAGE_H)   // 36864 halves = 73728 B

// Scratch
__device__ __align__(16) float  g_qr[S * H * D];            // roped Q, scaled log2e/8
__device__ __align__(16) __half g_kh[(size_t)H * NKV * D];  // window K fp16 [h][key][d]
__device__ __align__(16) __half g_vh[(size_t)H * NKV * D];  // window V fp16 [h][key][d]
__device__ __align__(16) float  g_po[NSPLIT * S * H * D];   // partial O
__device__ __align__(16) float  g_l[NSPLIT * S * H];        // partial denom

// ---------------------------------------------------------------------------
// Helpers
// ---------------------------------------------------------------------------
__device__ __forceinline__ uint32_t cvt_f16x2(float hi, float lo) {
    uint32_t r;
    asm("cvt.rn.f16x2.f32 %0, %1, %2;" : "=r"(r) : "f"(hi), "f"(lo));
    return r;
}
__device__ __forceinline__ uint32_t ex2_f16x2(uint32_t x) {
    uint32_t y;
    asm("ex2.approx.f16x2 %0, %1;" : "=r"(y) : "r"(x));
    return y;
}
__device__ __forceinline__ void mma_f16(float* c, const uint32_t* a, uint32_t b0, uint32_t b1) {
    asm volatile(
        "mma.sync.aligned.m16n8k16.row.col.f32.f16.f16.f32 "
        "{%0,%1,%2,%3}, {%4,%5,%6,%7}, {%8,%9}, {%0,%1,%2,%3};\n"
        : "+f"(c[0]), "+f"(c[1]), "+f"(c[2]), "+f"(c[3])
        : "r"(a[0]), "r"(a[1]), "r"(a[2]), "r"(a[3]), "r"(b0), "r"(b1));
}
__device__ __forceinline__ void ldsm_x4(uint32_t addr, uint32_t& r0, uint32_t& r1,
                                        uint32_t& r2, uint32_t& r3) {
    asm volatile("ldmatrix.sync.aligned.m8n8.x4.shared.b16 {%0,%1,%2,%3}, [%4];"
                 : "=r"(r0), "=r"(r1), "=r"(r2), "=r"(r3) : "r"(addr));
}
__device__ __forceinline__ void ldsm_x4_t(uint32_t addr, uint32_t& r0, uint32_t& r1,
                                          uint32_t& r2, uint32_t& r3) {
    asm volatile("ldmatrix.sync.aligned.m8n8.x4.trans.shared.b16 {%0,%1,%2,%3}, [%4];"
                 : "=r"(r0), "=r"(r1), "=r"(r2), "=r"(r3) : "r"(addr));
}
__device__ __forceinline__ void ldsm_x2_t(uint32_t addr, uint32_t& r0, uint32_t& r1) {
    asm volatile("ldmatrix.sync.aligned.m8n8.x2.trans.shared.b16 {%0,%1}, [%2];"
                 : "=r"(r0), "=r"(r1) : "r"(addr));
}
__device__ __forceinline__ void cp16(uint32_t smem_addr, const void* gptr) {
    asm volatile("cp.async.cg.shared.global [%0], [%1], 16;"
                 :: "r"(smem_addr), "l"(gptr));
}
#define CP_COMMIT() asm volatile("cp.async.commit_group;" ::: "memory")
#define CP_WAIT(N)  asm volatile("cp.async.wait_group %0;" :: "n"(N) : "memory")

// ---------------------------------------------------------------------------
// Prep 1: RoPE. Q -> g_qr (fp32, scaled). New K/V -> g_kh/g_vh[h][SPLIT+s].
// ---------------------------------------------------------------------------
__global__ void rope_prep(const float* __restrict__ q, const float* __restrict__ k,
                          const float* __restrict__ v,
                          const float* __restrict__ fc, const float* __restrict__ fs) {
    const float SC = 1.4426950408889634f * 0.125f;
    int idx = blockIdx.x * blockDim.x + threadIdx.x;
    if (idx >= S * H * 32) return;
    int p = idx & 31;
    int h = (idx >> 5) & 15;
    int s = idx >> 9;
    int pos = START_FRAME + s;
    float c  = fc[pos * 64 + 2 * p];
    float sn = fs[pos * 64 + 2 * p];
    int base = (s * H + h) * D + 2 * p;
    float q1 = q[base], q2 = q[base + 1];
    g_qr[base]     = (q1 * c - q2 * sn) * SC;
    g_qr[base + 1] = (q2 * c + q1 * sn) * SC;
    float k1 = k[base], k2 = k[base + 1];
    size_t dst = ((size_t)h * NKV + SPLIT + s) * D + 2 * p;
    *(uint32_t*)&g_kh[dst] = cvt_f16x2(k2 * c + k1 * sn, k1 * c - k2 * sn);
    float2 vv = *(const float2*)&v[base];
    *(uint32_t*)&g_vh[dst] = cvt_f16x2(vv.y, vv.x);
}

// ---------------------------------------------------------------------------
// Prep 2: cache K,V (rolled region) -> g_kh/g_vh[h][0..SPLIT), fp16
// ---------------------------------------------------------------------------
__global__ void conv_kv(const float* __restrict__ cache_k,
                        const float* __restrict__ cache_v) {
    int i4 = blockIdx.x * blockDim.x + threadIdx.x;   // SPLIT*H*16
    if (i4 >= SPLIT * H * 16) return;
    int c4 = (i4 & 15) << 2;
    int h  = (i4 >> 4) & 15;
    int j  = i4 >> 8;
    size_t src = (size_t)(CACHE_OFF + j) * (H * D) + h * D + c4;
    float4 kk = *(const float4*)&cache_k[src];
    float4 vv = *(const float4*)&cache_v[src];
    size_t dst = ((size_t)h * NKV + j) * D + c4;
    *(uint2*)&g_kh[dst] = make_uint2(cvt_f16x2(kk.y, kk.x), cvt_f16x2(kk.w, kk.z));
    *(uint2*)&g_vh[dst] = make_uint2(cvt_f16x2(vv.y, vv.x), cvt_f16x2(vv.w, vv.z));
}

// ---------------------------------------------------------------------------
// Flash attention: fp16 mma m16n8k16, ldmatrix A/B (+.trans for V), 3-stage
// cp.async, L via ones-column MMA, f16x2 softmax. Q frags hoisted (invariant).
// grid = (8, 16, 8) = 1024 CTAs, block = 128 (4 warps x 32 q-rows), 3 CTAs/SM.
// ---------------------------------------------------------------------------
__device__ __forceinline__ void prefetch_tile(uint32_t kbase, uint32_t vbase,
                                              int tid, int h, int kt) {
    const char* ksrc = (const char*)&g_kh[((size_t)h * NKV + (size_t)kt * BN) * D];
    const char* vsrc = (const char*)&g_vh[((size_t)h * NKV + (size_t)kt * BN) * D];
    #pragma unroll
    for (int g = 0; g < 4; g++) {
        int idx = tid + g * 128;
        int r = idx >> 3, c = idx & 7;
        uint32_t off = (uint32_t)(r * KS + c * 8) * 2;
        cp16(kbase + off, ksrc + (size_t)idx * 16);
        cp16(vbase + off, vsrc + (size_t)idx * 16);
    }
}

__global__ __launch_bounds__(128, 3) void attn_fp16() {
    extern __shared__ __align__(16) __half smem[];

    const int h     = blockIdx.y;
    const int q0    = blockIdx.x * BM;
    const int split = blockIdx.z;
    const int tid   = threadIdx.x;
    const int warp  = tid >> 5;
    const int lane  = tid & 31;
    const int gid   = lane >> 2;
    const int tig   = lane & 3;
    const int kt0   = split * TPT;

    const uint32_t sb = (uint32_t)__cvta_generic_to_shared(smem);
    const uint32_t qbase = sb + Q_OFF * 2u;
    uint32_t kaddr[3], vaddr[3];
    #pragma unroll
    for (int t = 0; t < 3; t++) {
        kaddr[t] = sb + KOFF(t) * 2u;
        vaddr[t] = sb + VOFF(t) * 2u;
    }

    // K (non-trans B): bit4 -> +8 rows(n), bit3 -> +16B (k-octet)
    const uint32_t loffB =
        (uint32_t)((((lane >> 4) & 1) * 8 + (lane & 7)) * KS * 2 + ((lane >> 3) & 1) * 16);
    // Q (A-frag): lanes 0-15 rows 0-15 (k-lo 16B), 16-31 same rows k-hi
    const uint32_t loffA =
        (uint32_t)((lane & 15) * KS * 2 + ((lane >> 4) & 1) * 16);
    // V (.trans B from [key][dim]): bit3 -> +8 keys, bit4 -> +16B (dim-octet)
    const uint32_t loffBV =
        (uint32_t)((((lane >> 3) & 1) * 8 + (lane & 7)) * KS * 2 + ((lane >> 4) & 1) * 16);
    // L ones-column (.trans x2): keys via bit3, dims 64-71 (byte 128)
    const uint32_t loffLV =
        (uint32_t)((((lane >> 3) & 1) * 8 + (lane & 7)) * KS * 2 + 128);

    // prologue: prefetch tiles 0,1
    prefetch_tile(kaddr[0], vaddr[0], tid, h, kt0);
    CP_COMMIT();
    prefetch_tile(kaddr[1], vaddr[1], tid, h, kt0 + 1);
    CP_COMMIT();

    // stage Q (fp32 -> fp16) rows 0..127
    {
        const float* qsrc = &g_qr[(size_t)q0 * (H * D) + h * D];
        #pragma unroll
        for (int g = 0; g < 8; g++) {
            int i = tid + g * 128;
            int r = i >> 3, c8 = (i & 7) * 8;
            float4 a = *(const float4*)&qsrc[(size_t)r * (H * D) + c8];
            float4 b = *(const float4*)&qsrc[(size_t)r * (H * D) + c8 + 4];
            *(uint4*)&smem[Q_OFF + r * KS + c8] = make_uint4(
                cvt_f16x2(a.y, a.x), cvt_f16x2(a.w, a.z),
                cvt_f16x2(b.y, b.x), cvt_f16x2(b.w, b.z));
        }
    }
    // ones-column (dim 64) / zeros (65-71) in all 3 V buffers
    {
        const __half one = __float2half(1.0f), zero = __float2half(0.0f);
        for (int i = tid; i < 3 * 64 * 8; i += 128) {
            int t = i >> 9, rem = i & 511;
            int key = rem >> 3, dd = 64 + (rem & 7);
            smem[VOFF(t) + key * KS + dd] = (dd == 64) ? one : zero;
        }
    }
    __syncthreads();   // Q staged; load invariant A-fragments once

    uint32_t qa[2][4][4];
    #pragma unroll
    for (int mt = 0; mt < 2; mt++) {
        uint32_t rowbase = qbase + (uint32_t)((warp * 32 + mt * 16) * KS * 2) + loffA;
        #pragma unroll
        for (int kk = 0; kk < 4; kk++)
            ldsm_x4(rowbase + (uint32_t)(kk * 32),
                    qa[mt][kk][0], qa[mt][kk][1], qa[mt][kk][2], qa[mt][kk][3]);
    }

    float o[2][8][4];
    #pragma unroll
    for (int mt = 0; mt < 2; mt++)
        #pragma unroll
        for (int nn = 0; nn < 8; nn++)
            o[mt][nn][0] = o[mt][nn][1] = o[mt][nn][2] = o[mt][nn][3] = 0.f;
    float oL[2][4];
    #pragma unroll
    for (int mt = 0; mt < 2; mt++)
        oL[mt][0] = oL[mt][1] = oL[mt][2] = oL[mt][3] = 0.f;

    int cur = 0, nxt = 2;      // buffer for tile j; buffer to prefetch (j+2)
    for (int j = 0; j < TPT; j++) {
        if (j + 1 < TPT) { CP_WAIT(1); } else { CP_WAIT(0); }
        __syncthreads();       // tile j visible; buf[nxt] consumed (iter j-1)

        if (j + 2 < TPT) {
            prefetch_tile(kaddr[nxt], vaddr[nxt], tid, h, kt0 + j + 2);
            CP_COMMIT();
        }

        // ---- MMA1 + per-nnp softmax -> pa  (nnp = key-block of 16) ----
        uint32_t pa[2][4][4];
        #pragma unroll
        for (int nnp = 0; nnp < 4; nnp++) {
            float sacc[2][2][4];
            #pragma unroll
            for (int mt = 0; mt < 2; mt++)
                #pragma unroll
                for (int nn = 0; nn < 2; nn++)
                    sacc[mt][nn][0] = sacc[mt][nn][1] = sacc[mt][nn][2] = sacc[mt][nn][3] = 0.f;
            #pragma unroll
            for (int kk = 0; kk < 4; kk++) {
                uint32_t b0, b1, b2, b3;
                ldsm_x4(kaddr[cur] + loffB + (uint32_t)(nnp * 16 * KS * 2 + kk * 32),
                        b0, b1, b2, b3);
                mma_f16(sacc[0][0], qa[0][kk], b0, b1);
                mma_f16(sacc[0][1], qa[0][kk], b2, b3);
                mma_f16(sacc[1][0], qa[1][kk], b0, b1);
                mma_f16(sacc[1][1], qa[1][kk], b2, b3);
            }
            #pragma unroll
            for (int mt = 0; mt < 2; mt++) {
                pa[mt][nnp][0] = ex2_f16x2(cvt_f16x2(sacc[mt][0][1], sacc[mt][0][0]));
                pa[mt][nnp][1] = ex2_f16x2(cvt_f16x2(sacc[mt][0][3], sacc[mt][0][2]));
                pa[mt][nnp][2] = ex2_f16x2(cvt_f16x2(sacc[mt][1][1], sacc[mt][1][0]));
                pa[mt][nnp][3] = ex2_f16x2(cvt_f16x2(sacc[mt][1][3], sacc[mt][1][2]));
            }
        }

        // ---- MMA2: O += P * V  (V [key][dim] via .trans; nnp = dim-block) ----
        #pragma unroll
        for (int nnp = 0; nnp < 4; nnp++) {
            #pragma unroll
            for (int kk = 0; kk < 4; kk++) {
                uint32_t b0, b1, b2, b3;
                ldsm_x4_t(vaddr[cur] + loffBV + (uint32_t)(kk * 16 * KS * 2 + nnp * 32),
                          b0, b1, b2, b3);
                mma_f16(o[0][2 * nnp],     pa[0][kk], b0, b1);
                mma_f16(o[0][2 * nnp + 1], pa[0][kk], b2, b3);
                mma_f16(o[1][2 * nnp],     pa[1][kk], b0, b1);
                mma_f16(o[1][2 * nnp + 1], pa[1][kk], b2, b3);
            }
        }
        // ---- L: ones-column tile (exact fp32 accumulation) ----
        #pragma unroll
        for (int kk = 0; kk < 4; kk++) {
            uint32_t bL0, bL1;
            ldsm_x2_t(vaddr[cur] + loffLV + (uint32_t)(kk * 16 * KS * 2), bL0, bL1);
            mma_f16(oL[0], pa[0][kk], bL0, bL1);
            mma_f16(oL[1], pa[1][kk], bL0, bL1);
        }

        cur = (cur == 2) ? 0 : cur + 1;
        nxt = (nxt == 2) ? 0 : nxt + 1;
    }

    // ---- epilogue ----
    #pragma unroll
    for (int mt = 0; mt < 2; mt++) {
        int r = q0 + warp * 32 + mt * 16 + gid;
        size_t b0 = ((size_t)split * S + r) * (H * D) + h * 64;
        size_t b1 = ((size_t)split * S + r + 8) * (H * D) + h * 64;
        #pragma unroll
        for (int nn = 0; nn < 8; nn++) {
            *(float2*)&g_po[b0 + nn * 8 + 2 * tig] = make_float2(o[mt][nn][0], o[mt][nn][1]);
            *(float2*)&g_po[b1 + nn * 8 + 2 * tig] = make_float2(o[mt][nn][2], o[mt][nn][3]);
        }
        if (tig == 0) {
            g_l[(size_t)split * (S * H) + (size_t)r * H + h]       = oL[mt][0];
            g_l[(size_t)split * (S * H) + (size_t)(r + 8) * H + h] = oL[mt][2];
        }
    }
}

// ---------------------------------------------------------------------------
// Merge splits: each thread handles 8 floats (2x float4) for deep MLP.
// ---------------------------------------------------------------------------
__global__ __launch_bounds__(256) void reduce_kernel(float* __restrict__ out) {
    int t = blockIdx.x * blockDim.x + threadIdx.x;   // S*H*D/8 threads
    if (t >= S * H * D / 8) return;
    int idx = t * 8;
    int h = (idx >> 6) & 15;
    int s = idx >> 10;
    int mlb = s * H + h;

    float4 n0 = make_float4(0.f, 0.f, 0.f, 0.f);
    float4 n1 = make_float4(0.f, 0.f, 0.f, 0.f);
    float den = 0.f;
    #pragma unroll
    for (int i = 0; i < NSPLIT; i++) {
        const float* p = &g_po[(size_t)i * (S * H * D) + idx];
        float4 a = *(const float4*)p;
        float4 b = *(const float4*)(p + 4);
        n0.x += a.x; n0.y += a.y; n0.z += a.z; n0.w += a.w;
        n1.x += b.x; n1.y += b.y; n1.z += b.z; n1.w += b.w;
        den += g_l[(size_t)i * (S * H) + mlb];
    }
    float r = 1.f / den;
    *(float4*)&out[idx]     = make_float4(n0.x * r, n0.y * r, n0.z * r, n0.w * r);
    *(float4*)&out[idx + 4] = make_float4(n1.x * r, n1.y * r, n1.z * r, n1.w * r);
}

// ---------------------------------------------------------------------------
extern "C" void kernel_launch(void* const* d_in, const int* in_sizes, int n_in,
                              void* d_out, int out_size) {
    const float* q  = (const float*)d_in[0];
    const float* k  = (const float*)d_in[1];
    const float* v  = (const float*)d_in[2];
    const float* ck = (const float*)d_in[3];
    const float* cv = (const float*)d_in[4];
    const float* fc = (const float*)d_in[5];
    const float* fs = (const float*)d_in[6];
    float* out = (float*)d_out;
    (void)in_sizes; (void)n_in; (void)out_size;

    rope_prep<<<(S * H * 32 + 255) / 256, 256>>>(q, k, v, fc, fs);
    conv_kv<<<(SPLIT * H * 16 + 255) / 256, 256>>>(ck, cv);

    cudaFuncSetAttribute(attn_fp16, cudaFuncAttributeMaxDynamicSharedMemorySize,
                         SM_HALVES * 2);
    dim3 grid(S / BM, H, NSPLIT);
    attn_fp16<<<grid, 128, SM_HALVES * 2>>>();

    reduce_kernel<<<(S * H * D / 8 + 255) / 256, 256>>>(out);
}

// round 10
// speedup vs baseline: 3.4826x; 1.0258x over previous
#include <cuda_runtime.h>
#include <cuda_fp16.h>
#include <cstdint>

// Problem constants
#define H 16
#define D 64
#define S 1024
#define START_FRAME 9728
#define NKV 8192
#define CACHE_OFF 2560
#define SPLIT 7168
#define BM 128
#define BN 64
#define NSPLIT 8
#define TPT (NKV / BN / NSPLIT)   // 16 kv tiles per CTA
#define KS 72                     // smem row stride in halves (144B, conflict-free)

// smem layout (halves): Q [128][72]; 3 stages of (K [64][72], V [64][72])
#define Q_OFF     0
#define TILE_H    4608            // 64*72
#define STAGE_H   (2 * TILE_H)
#define KOFF(t)   (9216 + (t) * STAGE_H)
#define VOFF(t)   (9216 + (t) * STAGE_H + TILE_H)
#define SM_HALVES (9216 + 3 * STAGE_H)   // 36864 halves = 73728 B

// Scratch
__device__ __align__(16) float  g_qr[S * H * D];            // roped Q, scaled log2e/8
__device__ __align__(16) __half g_kh[(size_t)H * NKV * D];  // window K fp16 [h][key][d]
__device__ __align__(16) __half g_vh[(size_t)H * NKV * D];  // window V fp16 [h][key][d]
__device__ __align__(16) __half g_po[(size_t)NSPLIT * S * H * D];  // partial O (fp16)
__device__ __align__(16) float  g_l[NSPLIT * S * H];        // partial denom (fp32)

// ---------------------------------------------------------------------------
// Helpers
// ---------------------------------------------------------------------------
__device__ __forceinline__ uint32_t cvt_f16x2(float hi, float lo) {
    uint32_t r;
    asm("cvt.rn.f16x2.f32 %0, %1, %2;" : "=r"(r) : "f"(hi), "f"(lo));
    return r;
}
__device__ __forceinline__ uint32_t ex2_f16x2(uint32_t x) {
    uint32_t y;
    asm("ex2.approx.f16x2 %0, %1;" : "=r"(y) : "r"(x));
    return y;
}
__device__ __forceinline__ void mma_f16(float* c, const uint32_t* a, uint32_t b0, uint32_t b1) {
    asm volatile(
        "mma.sync.aligned.m16n8k16.row.col.f32.f16.f16.f32 "
        "{%0,%1,%2,%3}, {%4,%5,%6,%7}, {%8,%9}, {%0,%1,%2,%3};\n"
        : "+f"(c[0]), "+f"(c[1]), "+f"(c[2]), "+f"(c[3])
        : "r"(a[0]), "r"(a[1]), "r"(a[2]), "r"(a[3]), "r"(b0), "r"(b1));
}
__device__ __forceinline__ void ldsm_x4(uint32_t addr, uint32_t& r0, uint32_t& r1,
                                        uint32_t& r2, uint32_t& r3) {
    asm volatile("ldmatrix.sync.aligned.m8n8.x4.shared.b16 {%0,%1,%2,%3}, [%4];"
                 : "=r"(r0), "=r"(r1), "=r"(r2), "=r"(r3) : "r"(addr));
}
__device__ __forceinline__ void ldsm_x4_t(uint32_t addr, uint32_t& r0, uint32_t& r1,
                                          uint32_t& r2, uint32_t& r3) {
    asm volatile("ldmatrix.sync.aligned.m8n8.x4.trans.shared.b16 {%0,%1,%2,%3}, [%4];"
                 : "=r"(r0), "=r"(r1), "=r"(r2), "=r"(r3) : "r"(addr));
}
__device__ __forceinline__ void ldsm_x2_t(uint32_t addr, uint32_t& r0, uint32_t& r1) {
    asm volatile("ldmatrix.sync.aligned.m8n8.x2.trans.shared.b16 {%0,%1}, [%2];"
                 : "=r"(r0), "=r"(r1) : "r"(addr));
}
__device__ __forceinline__ void cp16(uint32_t smem_addr, const void* gptr) {
    asm volatile("cp.async.cg.shared.global [%0], [%1], 16;"
                 :: "r"(smem_addr), "l"(gptr));
}
#define CP_COMMIT() asm volatile("cp.async.commit_group;" ::: "memory")
#define CP_WAIT(N)  asm volatile("cp.async.wait_group %0;" :: "n"(N) : "memory")

// ---------------------------------------------------------------------------
// Prep 1: RoPE. Q -> g_qr (fp32, scaled). New K/V -> g_kh/g_vh[h][SPLIT+s].
// ---------------------------------------------------------------------------
__global__ void rope_prep(const float* __restrict__ q, const float* __restrict__ k,
                          const float* __restrict__ v,
                          const float* __restrict__ fc, const float* __restrict__ fs) {
    const float SC = 1.4426950408889634f * 0.125f;
    int idx = blockIdx.x * blockDim.x + threadIdx.x;
    if (idx >= S * H * 32) return;
    int p = idx & 31;
    int h = (idx >> 5) & 15;
    int s = idx >> 9;
    int pos = START_FRAME + s;
    float c  = fc[pos * 64 + 2 * p];
    float sn = fs[pos * 64 + 2 * p];
    int base = (s * H + h) * D + 2 * p;
    float q1 = q[base], q2 = q[base + 1];
    g_qr[base]     = (q1 * c - q2 * sn) * SC;
    g_qr[base + 1] = (q2 * c + q1 * sn) * SC;
    float k1 = k[base], k2 = k[base + 1];
    size_t dst = ((size_t)h * NKV + SPLIT + s) * D + 2 * p;
    *(uint32_t*)&g_kh[dst] = cvt_f16x2(k2 * c + k1 * sn, k1 * c - k2 * sn);
    float2 vv = *(const float2*)&v[base];
    *(uint32_t*)&g_vh[dst] = cvt_f16x2(vv.y, vv.x);
}

// ---------------------------------------------------------------------------
// Prep 2: cache K,V (rolled region) -> g_kh/g_vh[h][0..SPLIT), fp16
// ---------------------------------------------------------------------------
__global__ void conv_kv(const float* __restrict__ cache_k,
                        const float* __restrict__ cache_v) {
    int i4 = blockIdx.x * blockDim.x + threadIdx.x;   // SPLIT*H*16
    if (i4 >= SPLIT * H * 16) return;
    int c4 = (i4 & 15) << 2;
    int h  = (i4 >> 4) & 15;
    int j  = i4 >> 8;
    size_t src = (size_t)(CACHE_OFF + j) * (H * D) + h * D + c4;
    float4 kk = *(const float4*)&cache_k[src];
    float4 vv = *(const float4*)&cache_v[src];
    size_t dst = ((size_t)h * NKV + j) * D + c4;
    *(uint2*)&g_kh[dst] = make_uint2(cvt_f16x2(kk.y, kk.x), cvt_f16x2(kk.w, kk.z));
    *(uint2*)&g_vh[dst] = make_uint2(cvt_f16x2(vv.y, vv.x), cvt_f16x2(vv.w, vv.z));
}

// ---------------------------------------------------------------------------
// Flash attention: fp16 mma m16n8k16, ldmatrix A/B (+.trans for V), 3-stage
// cp.async, fused per-16-key-block mainloop (MMA1 -> softmax -> MMA2+L),
// L via ones-column MMA, f16x2 softmax.
// grid = (8, 16, 8) = 1024 CTAs, block = 128 (4 warps x 32 q-rows), 3 CTAs/SM.
// ---------------------------------------------------------------------------
__device__ __forceinline__ void prefetch_tile(uint32_t kbase, uint32_t vbase,
                                              int tid, int h, int kt) {
    const char* ksrc = (const char*)&g_kh[((size_t)h * NKV + (size_t)kt * BN) * D];
    const char* vsrc = (const char*)&g_vh[((size_t)h * NKV + (size_t)kt * BN) * D];
    #pragma unroll
    for (int g = 0; g < 4; g++) {
        int idx = tid + g * 128;
        int r = idx >> 3, c = idx & 7;
        uint32_t off = (uint32_t)(r * KS + c * 8) * 2;
        cp16(kbase + off, ksrc + (size_t)idx * 16);
        cp16(vbase + off, vsrc + (size_t)idx * 16);
    }
}

__global__ __launch_bounds__(128, 3) void attn_fp16() {
    extern __shared__ __align__(16) __half smem[];

    const int h     = blockIdx.y;
    const int q0    = blockIdx.x * BM;
    const int split = blockIdx.z;
    const int tid   = threadIdx.x;
    const int warp  = tid >> 5;
    const int lane  = tid & 31;
    const int gid   = lane >> 2;
    const int tig   = lane & 3;
    const int kt0   = split * TPT;

    const uint32_t sb = (uint32_t)__cvta_generic_to_shared(smem);
    const uint32_t qbase = sb + Q_OFF * 2u;
    uint32_t kaddr[3], vaddr[3];
    #pragma unroll
    for (int t = 0; t < 3; t++) {
        kaddr[t] = sb + KOFF(t) * 2u;
        vaddr[t] = sb + VOFF(t) * 2u;
    }

    // K (non-trans B): bit4 -> +8 rows(n), bit3 -> +16B (k-octet)
    const uint32_t loffB =
        (uint32_t)((((lane >> 4) & 1) * 8 + (lane & 7)) * KS * 2 + ((lane >> 3) & 1) * 16);
    // Q (A-frag): lanes 0-15 rows 0-15 (k-lo 16B), 16-31 same rows k-hi
    const uint32_t loffA =
        (uint32_t)((lane & 15) * KS * 2 + ((lane >> 4) & 1) * 16);
    // V (.trans B from [key][dim]): bit3 -> +8 keys, bit4 -> +16B (dim-octet)
    const uint32_t loffBV =
        (uint32_t)((((lane >> 3) & 1) * 8 + (lane & 7)) * KS * 2 + ((lane >> 4) & 1) * 16);
    // L ones-column (.trans x2): keys via bit3, dims 64-71 (byte 128)
    const uint32_t loffLV =
        (uint32_t)((((lane >> 3) & 1) * 8 + (lane & 7)) * KS * 2 + 128);

    // prologue: prefetch tiles 0,1
    prefetch_tile(kaddr[0], vaddr[0], tid, h, kt0);
    CP_COMMIT();
    prefetch_tile(kaddr[1], vaddr[1], tid, h, kt0 + 1);
    CP_COMMIT();

    // stage Q (fp32 -> fp16) rows 0..127
    {
        const float* qsrc = &g_qr[(size_t)q0 * (H * D) + h * D];
        #pragma unroll
        for (int g = 0; g < 8; g++) {
            int i = tid + g * 128;
            int r = i >> 3, c8 = (i & 7) * 8;
            float4 a = *(const float4*)&qsrc[(size_t)r * (H * D) + c8];
            float4 b = *(const float4*)&qsrc[(size_t)r * (H * D) + c8 + 4];
            *(uint4*)&smem[Q_OFF + r * KS + c8] = make_uint4(
                cvt_f16x2(a.y, a.x), cvt_f16x2(a.w, a.z),
                cvt_f16x2(b.y, b.x), cvt_f16x2(b.w, b.z));
        }
    }
    // ones-column (dim 64) / zeros (65-71) in all 3 V buffers
    {
        const __half one = __float2half(1.0f), zero = __float2half(0.0f);
        for (int i = tid; i < 3 * 64 * 8; i += 128) {
            int t = i >> 9, rem = i & 511;
            int key = rem >> 3, dd = 64 + (rem & 7);
            smem[VOFF(t) + key * KS + dd] = (dd == 64) ? one : zero;
        }
    }
    __syncthreads();   // Q staged; load invariant A-fragments once

    uint32_t qa[2][4][4];
    #pragma unroll
    for (int mt = 0; mt < 2; mt++) {
        uint32_t rowbase = qbase + (uint32_t)((warp * 32 + mt * 16) * KS * 2) + loffA;
        #pragma unroll
        for (int kk = 0; kk < 4; kk++)
            ldsm_x4(rowbase + (uint32_t)(kk * 32),
                    qa[mt][kk][0], qa[mt][kk][1], qa[mt][kk][2], qa[mt][kk][3]);
    }

    float o[2][8][4];
    #pragma unroll
    for (int mt = 0; mt < 2; mt++)
        #pragma unroll
        for (int nn = 0; nn < 8; nn++)
            o[mt][nn][0] = o[mt][nn][1] = o[mt][nn][2] = o[mt][nn][3] = 0.f;
    float oL[2][4];
    #pragma unroll
    for (int mt = 0; mt < 2; mt++)
        oL[mt][0] = oL[mt][1] = oL[mt][2] = oL[mt][3] = 0.f;

    int cur = 0, nxt = 2;      // buffer for tile j; buffer to prefetch (j+2)
    for (int j = 0; j < TPT; j++) {
        if (j + 1 < TPT) { CP_WAIT(1); } else { CP_WAIT(0); }
        __syncthreads();       // tile j visible; buf[nxt] consumed (iter j-1)

        if (j + 2 < TPT) {
            prefetch_tile(kaddr[nxt], vaddr[nxt], tid, h, kt0 + j + 2);
            CP_COMMIT();
        }

        // ---- fused per-16-key block: MMA1 -> softmax -> L + MMA2 ----
        #pragma unroll
        for (int kb = 0; kb < 4; kb++) {
            // MMA1: S(block kb) = Q * K^T, contraction over d (4 k16-steps)
            float sacc[2][2][4];
            #pragma unroll
            for (int mt = 0; mt < 2; mt++)
                #pragma unroll
                for (int nn = 0; nn < 2; nn++)
                    sacc[mt][nn][0] = sacc[mt][nn][1] = sacc[mt][nn][2] = sacc[mt][nn][3] = 0.f;
            #pragma unroll
            for (int kd = 0; kd < 4; kd++) {
                uint32_t b0, b1, b2, b3;
                ldsm_x4(kaddr[cur] + loffB + (uint32_t)(kb * 16 * KS * 2 + kd * 32),
                        b0, b1, b2, b3);
                mma_f16(sacc[0][0], qa[0][kd], b0, b1);
                mma_f16(sacc[0][1], qa[0][kd], b2, b3);
                mma_f16(sacc[1][0], qa[1][kd], b0, b1);
                mma_f16(sacc[1][1], qa[1][kd], b2, b3);
            }
            // softmax: p = 2^s (f16x2), A-fragment layout for MMA2
            uint32_t pa[2][4];
            #pragma unroll
            for (int mt = 0; mt < 2; mt++) {
                pa[mt][0] = ex2_f16x2(cvt_f16x2(sacc[mt][0][1], sacc[mt][0][0]));
                pa[mt][1] = ex2_f16x2(cvt_f16x2(sacc[mt][0][3], sacc[mt][0][2]));
                pa[mt][2] = ex2_f16x2(cvt_f16x2(sacc[mt][1][1], sacc[mt][1][0]));
                pa[mt][3] = ex2_f16x2(cvt_f16x2(sacc[mt][1][3], sacc[mt][1][2]));
            }
            // L: ones-column (exact fp32 accumulation)
            {
                uint32_t bL0, bL1;
                ldsm_x2_t(vaddr[cur] + loffLV + (uint32_t)(kb * 16 * KS * 2), bL0, bL1);
                mma_f16(oL[0], pa[0], bL0, bL1);
                mma_f16(oL[1], pa[1], bL0, bL1);
            }
            // MMA2: O += P(block kb) * V(block kb), all 4 dim-blocks
            #pragma unroll
            for (int nnp = 0; nnp < 4; nnp++) {
                uint32_t b0, b1, b2, b3;
                ldsm_x4_t(vaddr[cur] + loffBV + (uint32_t)(kb * 16 * KS * 2 + nnp * 32),
                          b0, b1, b2, b3);
                mma_f16(o[0][2 * nnp],     pa[0], b0, b1);
                mma_f16(o[0][2 * nnp + 1], pa[0], b2, b3);
                mma_f16(o[1][2 * nnp],     pa[1], b0, b1);
                mma_f16(o[1][2 * nnp + 1], pa[1], b2, b3);
            }
        }

        cur = (cur == 2) ? 0 : cur + 1;
        nxt = (nxt == 2) ? 0 : nxt + 1;
    }

    // ---- epilogue: fp16 partial O, fp32 L ----
    #pragma unroll
    for (int mt = 0; mt < 2; mt++) {
        int r = q0 + warp * 32 + mt * 16 + gid;
        size_t b0 = ((size_t)split * S + r) * (H * D) + h * 64;
        size_t b1 = ((size_t)split * S + r + 8) * (H * D) + h * 64;
        #pragma unroll
        for (int nn = 0; nn < 8; nn++) {
            *(uint32_t*)&g_po[b0 + nn * 8 + 2 * tig] = cvt_f16x2(o[mt][nn][1], o[mt][nn][0]);
            *(uint32_t*)&g_po[b1 + nn * 8 + 2 * tig] = cvt_f16x2(o[mt][nn][3], o[mt][nn][2]);
        }
        if (tig == 0) {
            g_l[(size_t)split * (S * H) + (size_t)r * H + h]       = oL[mt][0];
            g_l[(size_t)split * (S * H) + (size_t)(r + 8) * H + h] = oL[mt][2];
        }
    }
}

// ---------------------------------------------------------------------------
// Merge splits: fp16 partials (8 halves = uint4 per split), fp32 accumulate.
// ---------------------------------------------------------------------------
__global__ __launch_bounds__(256) void reduce_kernel(float* __restrict__ out) {
    int t = blockIdx.x * blockDim.x + threadIdx.x;   // S*H*D/8 threads
    if (t >= S * H * D / 8) return;
    int idx = t * 8;
    int h = (idx >> 6) & 15;
    int s = idx >> 10;
    int mlb = s * H + h;

    float acc[8] = {0.f, 0.f, 0.f, 0.f, 0.f, 0.f, 0.f, 0.f};
    float den = 0.f;
    #pragma unroll
    for (int i = 0; i < NSPLIT; i++) {
        uint4 pk = *(const uint4*)&g_po[(size_t)i * (S * H * D) + idx];
        float2 a0 = __half22float2(*(const __half2*)&pk.x);
        float2 a1 = __half22float2(*(const __half2*)&pk.y);
        float2 a2 = __half22float2(*(const __half2*)&pk.z);
        float2 a3 = __half22float2(*(const __half2*)&pk.w);
        acc[0] += a0.x; acc[1] += a0.y; acc[2] += a1.x; acc[3] += a1.y;
        acc[4] += a2.x; acc[5] += a2.y; acc[6] += a3.x; acc[7] += a3.y;
        den += g_l[(size_t)i * (S * H) + mlb];
    }
    float r = 1.f / den;
    *(float4*)&out[idx]     = make_float4(acc[0] * r, acc[1] * r, acc[2] * r, acc[3] * r);
    *(float4*)&out[idx + 4] = make_float4(acc[4] * r, acc[5] * r, acc[6] * r, acc[7] * r);
}

// ---------------------------------------------------------------------------
extern "C" void kernel_launch(void* const* d_in, const int* in_sizes, int n_in,
                              void* d_out, int out_size) {
    const float* q  = (const float*)d_in[0];
    const float* k  = (const float*)d_in[1];
    const float* v  = (const float*)d_in[2];
    const float* ck = (const float*)d_in[3];
    const float* cv = (const float*)d_in[4];
    const float* fc = (const float*)d_in[5];
    const float* fs = (const float*)d_in[6];
    float* out = (float*)d_out;
    (void)in_sizes; (void)n_in; (void)out_size;

    rope_prep<<<(S * H * 32 + 255) / 256, 256>>>(q, k, v, fc, fs);
    conv_kv<<<(SPLIT * H * 16 + 255) / 256, 256>>>(ck, cv);

    cudaFuncSetAttribute(attn_fp16, cudaFuncAttributeMaxDynamicSharedMemorySize,
                         SM_HALVES * 2);
    dim3 grid(S / BM, H, NSPLIT);
    attn_fp16<<<grid, 128, SM_HALVES * 2>>>();

    reduce_kernel<<<(S * H * D / 8 + 255) / 256, 256>>>(out);
}

// round 11
// speedup vs baseline: 3.5954x; 1.0324x over previous
#include <cuda_runtime.h>
#include <cuda_fp16.h>
#include <cstdint>

// Problem constants
#define H 16
#define D 64
#define S 1024
#define START_FRAME 9728
#define NKV 8192
#define CACHE_OFF 2560
#define SPLIT 7168
#define BM 128
#define BN 64
#define NSPLIT 8
#define TPT (NKV / BN / NSPLIT)   // 16 kv tiles per CTA
#define KS 72                     // smem row stride in halves (144B, conflict-free)

// smem: 4 stages of (K [64][72] | V [64][72]) = 4 x 9216 halves = 73728 B.
// Q (128 x 64 halves) is staged into stage 0 (halves 0-63 of 128 rows) during
// the prologue, consumed into registers, then stage 0 joins the ring.
#define TILE_H    4608            // 64*72
#define STAGE_H   (2 * TILE_H)    // 9216 halves
#define SM_HALVES (4 * STAGE_H)   // 36864 halves = 73728 B

// Scratch
__device__ __align__(16) __half g_qh[(size_t)H * S * D];    // roped Q fp16 [h][s][d]
__device__ __align__(16) __half g_kh[(size_t)H * NKV * D];  // window K fp16 [h][key][d]
__device__ __align__(16) __half g_vh[(size_t)H * NKV * D];  // window V fp16 [h][key][d]
__device__ __align__(16) __half g_po[(size_t)NSPLIT * S * H * D];  // partial O (fp16)
__device__ __align__(16) float  g_l[NSPLIT * S * H];        // partial denom (fp32)

// ---------------------------------------------------------------------------
// Helpers
// ---------------------------------------------------------------------------
__device__ __forceinline__ uint32_t cvt_f16x2(float hi, float lo) {
    uint32_t r;
    asm("cvt.rn.f16x2.f32 %0, %1, %2;" : "=r"(r) : "f"(hi), "f"(lo));
    return r;
}
__device__ __forceinline__ uint32_t ex2_f16x2(uint32_t x) {
    uint32_t y;
    asm("ex2.approx.f16x2 %0, %1;" : "=r"(y) : "r"(x));
    return y;
}
__device__ __forceinline__ void mma_f16(float* c, const uint32_t* a, uint32_t b0, uint32_t b1) {
    asm volatile(
        "mma.sync.aligned.m16n8k16.row.col.f32.f16.f16.f32 "
        "{%0,%1,%2,%3}, {%4,%5,%6,%7}, {%8,%9}, {%0,%1,%2,%3};\n"
        : "+f"(c[0]), "+f"(c[1]), "+f"(c[2]), "+f"(c[3])
        : "r"(a[0]), "r"(a[1]), "r"(a[2]), "r"(a[3]), "r"(b0), "r"(b1));
}
__device__ __forceinline__ void ldsm_x4(uint32_t addr, uint32_t& r0, uint32_t& r1,
                                        uint32_t& r2, uint32_t& r3) {
    asm volatile("ldmatrix.sync.aligned.m8n8.x4.shared.b16 {%0,%1,%2,%3}, [%4];"
                 : "=r"(r0), "=r"(r1), "=r"(r2), "=r"(r3) : "r"(addr));
}
__device__ __forceinline__ void ldsm_x4_t(uint32_t addr, uint32_t& r0, uint32_t& r1,
                                          uint32_t& r2, uint32_t& r3) {
    asm volatile("ldmatrix.sync.aligned.m8n8.x4.trans.shared.b16 {%0,%1,%2,%3}, [%4];"
                 : "=r"(r0), "=r"(r1), "=r"(r2), "=r"(r3) : "r"(addr));
}
__device__ __forceinline__ void ldsm_x2_t(uint32_t addr, uint32_t& r0, uint32_t& r1) {
    asm volatile("ldmatrix.sync.aligned.m8n8.x2.trans.shared.b16 {%0,%1}, [%2];"
                 : "=r"(r0), "=r"(r1) : "r"(addr));
}
__device__ __forceinline__ void cp16(uint32_t smem_addr, const void* gptr) {
    asm volatile("cp.async.cg.shared.global [%0], [%1], 16;"
                 :: "r"(smem_addr), "l"(gptr));
}
#define CP_COMMIT() asm volatile("cp.async.commit_group;" ::: "memory")
#define CP_WAIT(N)  asm volatile("cp.async.wait_group %0;" :: "n"(N) : "memory")

// ---------------------------------------------------------------------------
// Fused prep: blocks [0, ropeBlocks) do RoPE (Q->g_qh scaled fp16; new K/V ->
// g_kh/g_vh at [SPLIT+s]); remaining blocks convert the rolled cache region.
// All paths float4-in / vector-out.
// ---------------------------------------------------------------------------
#define ROPE_ITEMS (S * H * 16)       // one float4 (2 rope pairs) per item
#define CONV_ITEMS (SPLIT * H * 16)   // one float4 per item

__global__ void prep_fused(const float* __restrict__ q, const float* __restrict__ k,
                           const float* __restrict__ v,
                           const float* __restrict__ cache_k,
                           const float* __restrict__ cache_v,
                           const float* __restrict__ fc, const float* __restrict__ fs) {
    const float SC = 1.4426950408889634f * 0.125f;
    int idx = blockIdx.x * blockDim.x + threadIdx.x;
    if (idx < ROPE_ITEMS) {
        int c4 = (idx & 15) << 2;        // dim base (0,4,...,60)
        int h  = (idx >> 4) & 15;
        int s  = idx >> 8;
        int pos = START_FRAME + s;
        float4 f_c = *(const float4*)&fc[pos * 64 + c4];
        float4 f_s = *(const float4*)&fs[pos * 64 + c4];
        // pairs: dims (c4, c4+1) use f_c.x/f_s.x ; dims (c4+2, c4+3) use .z
        int base = (s * H + h) * D + c4;
        float4 qv = *(const float4*)&q[base];
        float4 kv = *(const float4*)&k[base];
        float4 vv = *(const float4*)&v[base];
        float qo0 = (qv.x * f_c.x - qv.y * f_s.x) * SC;
        float qo1 = (qv.y * f_c.x + qv.x * f_s.x) * SC;
        float qo2 = (qv.z * f_c.z - qv.w * f_s.z) * SC;
        float qo3 = (qv.w * f_c.z + qv.z * f_s.z) * SC;
        float ko0 = kv.x * f_c.x - kv.y * f_s.x;
        float ko1 = kv.y * f_c.x + kv.x * f_s.x;
        float ko2 = kv.z * f_c.z - kv.w * f_s.z;
        float ko3 = kv.w * f_c.z + kv.z * f_s.z;
        *(uint2*)&g_qh[((size_t)h * S + s) * D + c4] =
            make_uint2(cvt_f16x2(qo1, qo0), cvt_f16x2(qo3, qo2));
        size_t dst = ((size_t)h * NKV + SPLIT + s) * D + c4;
        *(uint2*)&g_kh[dst] = make_uint2(cvt_f16x2(ko1, ko0), cvt_f16x2(ko3, ko2));
        *(uint2*)&g_vh[dst] = make_uint2(cvt_f16x2(vv.y, vv.x), cvt_f16x2(vv.w, vv.z));
    } else {
        int i4 = idx - ROPE_ITEMS;
        if (i4 >= CONV_ITEMS) return;
        int c4 = (i4 & 15) << 2;
        int h  = (i4 >> 4) & 15;
        int j  = i4 >> 8;
        size_t src = (size_t)(CACHE_OFF + j) * (H * D) + h * D + c4;
        float4 kk = *(const float4*)&cache_k[src];
        float4 vv = *(const float4*)&cache_v[src];
        size_t dst = ((size_t)h * NKV + j) * D + c4;
        *(uint2*)&g_kh[dst] = make_uint2(cvt_f16x2(kk.y, kk.x), cvt_f16x2(kk.w, kk.z));
        *(uint2*)&g_vh[dst] = make_uint2(cvt_f16x2(vv.y, vv.x), cvt_f16x2(vv.w, vv.z));
    }
}

// ---------------------------------------------------------------------------
// Flash attention: fp16 mma m16n8k16, ldmatrix A/B (+.trans V), 4-stage ring
// cp.async (depth-3 prefetch), fused per-16-key block, ones-column L,
// f16x2 softmax, fully-async prologue (Q staged via cp.async into stage 0).
// grid = (8, 16, 8) = 1024 CTAs, block = 128 (4 warps x 32 q-rows), 3 CTAs/SM.
// ---------------------------------------------------------------------------
__device__ __forceinline__ void prefetch_tile(uint32_t kbase, uint32_t vbase,
                                              int tid, int h, int kt) {
    const char* ksrc = (const char*)&g_kh[((size_t)h * NKV + (size_t)kt * BN) * D];
    const char* vsrc = (const char*)&g_vh[((size_t)h * NKV + (size_t)kt * BN) * D];
    #pragma unroll
    for (int g = 0; g < 4; g++) {
        int idx = tid + g * 128;
        int r = idx >> 3, c = idx & 7;
        uint32_t off = (uint32_t)(r * KS + c * 8) * 2;
        cp16(kbase + off, ksrc + (size_t)idx * 16);
        cp16(vbase + off, vsrc + (size_t)idx * 16);
    }
}

__global__ __launch_bounds__(128, 3) void attn_fp16() {
    extern __shared__ __align__(16) __half smem[];

    const int h     = blockIdx.y;
    const int q0    = blockIdx.x * BM;
    const int split = blockIdx.z;
    const int tid   = threadIdx.x;
    const int warp  = tid >> 5;
    const int lane  = tid & 31;
    const int gid   = lane >> 2;
    const int tig   = lane & 3;
    const int kt0   = split * TPT;

    const uint32_t sb = (uint32_t)__cvta_generic_to_shared(smem);
    uint32_t kaddr[4], vaddr[4];
    #pragma unroll
    for (int t = 0; t < 4; t++) {
        kaddr[t] = sb + (uint32_t)(t * STAGE_H) * 2u;
        vaddr[t] = kaddr[t] + (uint32_t)TILE_H * 2u;
    }

    // K (non-trans B): bit4 -> +8 rows(n), bit3 -> +16B (k-octet)
    const uint32_t loffB =
        (uint32_t)((((lane >> 4) & 1) * 8 + (lane & 7)) * KS * 2 + ((lane >> 3) & 1) * 16);
    // Q (A-frag): lanes 0-15 rows 0-15 (k-lo 16B), 16-31 same rows k-hi
    const uint32_t loffA =
        (uint32_t)((lane & 15) * KS * 2 + ((lane >> 4) & 1) * 16);
    // V (.trans B from [key][dim]): bit3 -> +8 keys, bit4 -> +16B (dim-octet)
    const uint32_t loffBV =
        (uint32_t)((((lane >> 3) & 1) * 8 + (lane & 7)) * KS * 2 + ((lane >> 4) & 1) * 16);
    // L ones-column (.trans x2): keys via bit3, dims 64-71 (byte 128)
    const uint32_t loffLV =
        (uint32_t)((((lane >> 3) & 1) * 8 + (lane & 7)) * KS * 2 + 128);

    // ---- prologue: async Q into stage 0 (halves 0-63 of 128 rows) ----
    {
        const char* qsrc = (const char*)&g_qh[((size_t)h * S + q0) * D];
        #pragma unroll
        for (int g = 0; g < 8; g++) {
            int idx = tid + g * 128;
            int r = idx >> 3, c = idx & 7;
            cp16(sb + (uint32_t)(r * KS + c * 8) * 2, qsrc + (size_t)idx * 16);
        }
        CP_COMMIT();   // group: Q
    }
    // tiles 0,1,2 into stages 1,2,3 (tile j lives in stage (j+1)&3)
    prefetch_tile(kaddr[1], vaddr[1], tid, h, kt0);     CP_COMMIT();
    prefetch_tile(kaddr[2], vaddr[2], tid, h, kt0 + 1); CP_COMMIT();
    prefetch_tile(kaddr[3], vaddr[3], tid, h, kt0 + 2); CP_COMMIT();

    // ones-column (dim 64) / zeros (65-71) in all 4 V areas (halves 64-71
    // are never touched by cp.async or Q staging)
    {
        const __half one = __float2half(1.0f), zero = __float2half(0.0f);
        for (int i = tid; i < 4 * 64 * 8; i += 128) {
            int t = i >> 9, rem = i & 511;
            int key = rem >> 3, dd = 64 + (rem & 7);
            smem[t * STAGE_H + TILE_H + key * KS + dd] = (dd == 64) ? one : zero;
        }
    }

    CP_WAIT(3);        // Q group retired
    __syncthreads();

    uint32_t qa[2][4][4];
    #pragma unroll
    for (int mt = 0; mt < 2; mt++) {
        uint32_t rowbase = sb + (uint32_t)((warp * 32 + mt * 16) * KS * 2) + loffA;
        #pragma unroll
        for (int kk = 0; kk < 4; kk++)
            ldsm_x4(rowbase + (uint32_t)(kk * 32),
                    qa[mt][kk][0], qa[mt][kk][1], qa[mt][kk][2], qa[mt][kk][3]);
    }

    float o[2][8][4];
    #pragma unroll
    for (int mt = 0; mt < 2; mt++)
        #pragma unroll
        for (int nn = 0; nn < 8; nn++)
            o[mt][nn][0] = o[mt][nn][1] = o[mt][nn][2] = o[mt][nn][3] = 0.f;
    float oL[2][4];
    #pragma unroll
    for (int mt = 0; mt < 2; mt++)
        oL[mt][0] = oL[mt][1] = oL[mt][2] = oL[mt][3] = 0.f;

    for (int j = 0; j < TPT; j++) {
        const int cs = (j + 1) & 3;        // stage holding tile j

        if (j + 2 < TPT)      { CP_WAIT(2); }
        else if (j + 1 < TPT) { CP_WAIT(1); }
        else                  { CP_WAIT(0); }
        __syncthreads();   // tile j visible to all; stage (j)&3 fully consumed
                           // (iter j-1) and qa loaded by all warps (j==0)

        if (j + 3 < TPT) {
            prefetch_tile(kaddr[j & 3], vaddr[j & 3], tid, h, kt0 + j + 3);
            CP_COMMIT();
        }

        // ---- fused per-16-key block: MMA1 -> softmax -> L + MMA2 ----
        #pragma unroll
        for (int kb = 0; kb < 4; kb++) {
            float sacc[2][2][4];
            #pragma unroll
            for (int mt = 0; mt < 2; mt++)
                #pragma unroll
                for (int nn = 0; nn < 2; nn++)
                    sacc[mt][nn][0] = sacc[mt][nn][1] = sacc[mt][nn][2] = sacc[mt][nn][3] = 0.f;
            #pragma unroll
            for (int kd = 0; kd < 4; kd++) {
                uint32_t b0, b1, b2, b3;
                ldsm_x4(kaddr[cs] + loffB + (uint32_t)(kb * 16 * KS * 2 + kd * 32),
                        b0, b1, b2, b3);
                mma_f16(sacc[0][0], qa[0][kd], b0, b1);
                mma_f16(sacc[0][1], qa[0][kd], b2, b3);
                mma_f16(sacc[1][0], qa[1][kd], b0, b1);
                mma_f16(sacc[1][1], qa[1][kd], b2, b3);
            }
            uint32_t pa[2][4];
            #pragma unroll
            for (int mt = 0; mt < 2; mt++) {
                pa[mt][0] = ex2_f16x2(cvt_f16x2(sacc[mt][0][1], sacc[mt][0][0]));
                pa[mt][1] = ex2_f16x2(cvt_f16x2(sacc[mt][0][3], sacc[mt][0][2]));
                pa[mt][2] = ex2_f16x2(cvt_f16x2(sacc[mt][1][1], sacc[mt][1][0]));
                pa[mt][3] = ex2_f16x2(cvt_f16x2(sacc[mt][1][3], sacc[mt][1][2]));
            }
            {
                uint32_t bL0, bL1;
                ldsm_x2_t(vaddr[cs] + loffLV + (uint32_t)(kb * 16 * KS * 2), bL0, bL1);
                mma_f16(oL[0], pa[0], bL0, bL1);
                mma_f16(oL[1], pa[1], bL0, bL1);
            }
            #pragma unroll
            for (int nnp = 0; nnp < 4; nnp++) {
                uint32_t b0, b1, b2, b3;
                ldsm_x4_t(vaddr[cs] + loffBV + (uint32_t)(kb * 16 * KS * 2 + nnp * 32),
                          b0, b1, b2, b3);
                mma_f16(o[0][2 * nnp],     pa[0], b0, b1);
                mma_f16(o[0][2 * nnp + 1], pa[0], b2, b3);
                mma_f16(o[1][2 * nnp],     pa[1], b0, b1);
                mma_f16(o[1][2 * nnp + 1], pa[1], b2, b3);
            }
        }
    }

    // ---- epilogue: fp16 partial O, fp32 L ----
    #pragma unroll
    for (int mt = 0; mt < 2; mt++) {
        int r = q0 + warp * 32 + mt * 16 + gid;
        size_t b0 = ((size_t)split * S + r) * (H * D) + h * 64;
        size_t b1 = ((size_t)split * S + r + 8) * (H * D) + h * 64;
        #pragma unroll
        for (int nn = 0; nn < 8; nn++) {
            *(uint32_t*)&g_po[b0 + nn * 8 + 2 * tig] = cvt_f16x2(o[mt][nn][1], o[mt][nn][0]);
            *(uint32_t*)&g_po[b1 + nn * 8 + 2 * tig] = cvt_f16x2(o[mt][nn][3], o[mt][nn][2]);
        }
        if (tig == 0) {
            g_l[(size_t)split * (S * H) + (size_t)r * H + h]       = oL[mt][0];
            g_l[(size_t)split * (S * H) + (size_t)(r + 8) * H + h] = oL[mt][2];
        }
    }
}

// ---------------------------------------------------------------------------
// Merge splits: fp16 partials, fp32 accumulate.
// ---------------------------------------------------------------------------
__global__ __launch_bounds__(256) void reduce_kernel(float* __restrict__ out) {
    int t = blockIdx.x * blockDim.x + threadIdx.x;   // S*H*D/8 threads
    if (t >= S * H * D / 8) return;
    int idx = t * 8;
    int h = (idx >> 6) & 15;
    int s = idx >> 10;
    int mlb = s * H + h;

    float acc[8] = {0.f, 0.f, 0.f, 0.f, 0.f, 0.f, 0.f, 0.f};
    float den = 0.f;
    #pragma unroll
    for (int i = 0; i < NSPLIT; i++) {
        uint4 pk = *(const uint4*)&g_po[(size_t)i * (S * H * D) + idx];
        float2 a0 = __half22float2(*(const __half2*)&pk.x);
        float2 a1 = __half22float2(*(const __half2*)&pk.y);
        float2 a2 = __half22float2(*(const __half2*)&pk.z);
        float2 a3 = __half22float2(*(const __half2*)&pk.w);
        acc[0] += a0.x; acc[1] += a0.y; acc[2] += a1.x; acc[3] += a1.y;
        acc[4] += a2.x; acc[5] += a2.y; acc[6] += a3.x; acc[7] += a3.y;
        den += g_l[(size_t)i * (S * H) + mlb];
    }
    float r = 1.f / den;
    *(float4*)&out[idx]     = make_float4(acc[0] * r, acc[1] * r, acc[2] * r, acc[3] * r);
    *(float4*)&out[idx + 4] = make_float4(acc[4] * r, acc[5] * r, acc[6] * r, acc[7] * r);
}

// ---------------------------------------------------------------------------
extern "C" void kernel_launch(void* const* d_in, const int* in_sizes, int n_in,
                              void* d_out, int out_size) {
    const float* q  = (const float*)d_in[0];
    const float* k  = (const float*)d_in[1];
    const float* v  = (const float*)d_in[2];
    const float* ck = (const float*)d_in[3];
    const float* cv = (const float*)d_in[4];
    const float* fc = (const float*)d_in[5];
    const float* fs = (const float*)d_in[6];
    float* out = (float*)d_out;
    (void)in_sizes; (void)n_in; (void)out_size;

    int prep_items = ROPE_ITEMS + CONV_ITEMS;
    prep_fused<<<(prep_items + 255) / 256, 256>>>(q, k, v, ck, cv, fc, fs);

    cudaFuncSetAttribute(attn_fp16, cudaFuncAttributeMaxDynamicSharedMemorySize,
                         SM_HALVES * 2);
    dim3 grid(S / BM, H, NSPLIT);
    attn_fp16<<<grid, 128, SM_HALVES * 2>>>();

    reduce_kernel<<<(S * H * D / 8 + 255) / 256, 256>>>(out);
}

// round 12
// speedup vs baseline: 3.6216x; 1.0073x over previous
#include <cuda_runtime.h>
#include <cuda_fp16.h>
#include <cstdint>

// Problem constants
#define H 16
#define D 64
#define S 1024
#define START_FRAME 9728
#define NKV 8192
#define CACHE_OFF 2560
#define SPLIT 7168
#define BM 128
#define BN 64
#define NSPLIT 8
#define TPT (NKV / BN / NSPLIT)   // 16 kv tiles per CTA
#define KS 72                     // smem row stride in halves (144B, conflict-free)

// smem: 4 stages of (K [64][72] | V [64][72]) = 73728 B. Q staged into stage 0.
#define TILE_H    4608            // 64*72
#define STAGE_H   (2 * TILE_H)    // 9216 halves
#define SM_HALVES (4 * STAGE_H)   // 36864 halves = 73728 B

// Scratch
__device__ __align__(16) __half g_qh[(size_t)H * S * D];    // roped Q fp16 [h][s][d]
__device__ __align__(16) __half g_kh[(size_t)H * NKV * D];  // window K fp16 [h][key][d]
__device__ __align__(16) __half g_vh[(size_t)H * NKV * D];  // window V fp16 [h][key][d]
__device__ __align__(16) __half g_po[(size_t)NSPLIT * S * H * D];  // partial O (fp16)
__device__ __align__(16) float  g_l[NSPLIT * S * H];        // partial denom (fp32)

// ---------------------------------------------------------------------------
// Helpers
// ---------------------------------------------------------------------------
__device__ __forceinline__ uint32_t cvt_f16x2(float hi, float lo) {
    uint32_t r;
    asm("cvt.rn.f16x2.f32 %0, %1, %2;" : "=r"(r) : "f"(hi), "f"(lo));
    return r;
}
__device__ __forceinline__ uint32_t ex2_f16x2(uint32_t x) {
    uint32_t y;
    asm("ex2.approx.f16x2 %0, %1;" : "=r"(y) : "r"(x));
    return y;
}
__device__ __forceinline__ void mma_f16(float* c, const uint32_t* a, uint32_t b0, uint32_t b1) {
    asm volatile(
        "mma.sync.aligned.m16n8k16.row.col.f32.f16.f16.f32 "
        "{%0,%1,%2,%3}, {%4,%5,%6,%7}, {%8,%9}, {%0,%1,%2,%3};\n"
        : "+f"(c[0]), "+f"(c[1]), "+f"(c[2]), "+f"(c[3])
        : "r"(a[0]), "r"(a[1]), "r"(a[2]), "r"(a[3]), "r"(b0), "r"(b1));
}
__device__ __forceinline__ void ldsm_x4(uint32_t addr, uint32_t& r0, uint32_t& r1,
                                        uint32_t& r2, uint32_t& r3) {
    asm volatile("ldmatrix.sync.aligned.m8n8.x4.shared.b16 {%0,%1,%2,%3}, [%4];"
                 : "=r"(r0), "=r"(r1), "=r"(r2), "=r"(r3) : "r"(addr));
}
__device__ __forceinline__ void ldsm_x4_t(uint32_t addr, uint32_t& r0, uint32_t& r1,
                                          uint32_t& r2, uint32_t& r3) {
    asm volatile("ldmatrix.sync.aligned.m8n8.x4.trans.shared.b16 {%0,%1,%2,%3}, [%4];"
                 : "=r"(r0), "=r"(r1), "=r"(r2), "=r"(r3) : "r"(addr));
}
__device__ __forceinline__ void ldsm_x2_t(uint32_t addr, uint32_t& r0, uint32_t& r1) {
    asm volatile("ldmatrix.sync.aligned.m8n8.x2.trans.shared.b16 {%0,%1}, [%2];"
                 : "=r"(r0), "=r"(r1) : "r"(addr));
}
__device__ __forceinline__ void cp16(uint32_t smem_addr, const void* gptr) {
    asm volatile("cp.async.cg.shared.global [%0], [%1], 16;"
                 :: "r"(smem_addr), "l"(gptr));
}
__device__ __forceinline__ void stg_cs_u32(void* gptr, uint32_t v) {
    asm volatile("st.global.cs.b32 [%0], %1;" :: "l"(gptr), "r"(v) : "memory");
}
#define CP_COMMIT() asm volatile("cp.async.commit_group;" ::: "memory")
#define CP_WAIT(N)  asm volatile("cp.async.wait_group %0;" :: "n"(N) : "memory")

// ---------------------------------------------------------------------------
// Fused prep, 8 elements (uint4 out) per thread.
// items [0, ROPE_ITEMS): RoPE Q->g_qh (scaled fp16), new K/V -> [SPLIT+s]
// items [ROPE_ITEMS, +CONV_ITEMS): rolled cache K/V -> [0..SPLIT)
// ---------------------------------------------------------------------------
#define ROPE_ITEMS (S * H * 8)
#define CONV_ITEMS (SPLIT * H * 8)

__global__ void prep_fused(const float* __restrict__ q, const float* __restrict__ k,
                           const float* __restrict__ v,
                           const float* __restrict__ cache_k,
                           const float* __restrict__ cache_v,
                           const float* __restrict__ fc, const float* __restrict__ fs) {
    const float SC = 1.4426950408889634f * 0.125f;
    int idx = blockIdx.x * blockDim.x + threadIdx.x;
    if (idx < ROPE_ITEMS) {
        int c8 = (idx & 7) << 3;         // dim base (0,8,...,56)
        int h  = (idx >> 3) & 15;
        int s  = idx >> 7;
        int pos = START_FRAME + s;
        float4 fc0 = *(const float4*)&fc[pos * 64 + c8];
        float4 fc1 = *(const float4*)&fc[pos * 64 + c8 + 4];
        float4 fs0 = *(const float4*)&fs[pos * 64 + c8];
        float4 fs1 = *(const float4*)&fs[pos * 64 + c8 + 4];
        int base = (s * H + h) * D + c8;
        float4 q0 = *(const float4*)&q[base];
        float4 q1 = *(const float4*)&q[base + 4];
        float4 k0 = *(const float4*)&k[base];
        float4 k1 = *(const float4*)&k[base + 4];
        float4 v0 = *(const float4*)&v[base];
        float4 v1 = *(const float4*)&v[base + 4];

        uint4 qo, ko, vo;
        qo.x = cvt_f16x2((q0.y * fc0.x + q0.x * fs0.x) * SC, (q0.x * fc0.x - q0.y * fs0.x) * SC);
        qo.y = cvt_f16x2((q0.w * fc0.z + q0.z * fs0.z) * SC, (q0.z * fc0.z - q0.w * fs0.z) * SC);
        qo.z = cvt_f16x2((q1.y * fc1.x + q1.x * fs1.x) * SC, (q1.x * fc1.x - q1.y * fs1.x) * SC);
        qo.w = cvt_f16x2((q1.w * fc1.z + q1.z * fs1.z) * SC, (q1.z * fc1.z - q1.w * fs1.z) * SC);
        ko.x = cvt_f16x2(k0.y * fc0.x + k0.x * fs0.x, k0.x * fc0.x - k0.y * fs0.x);
        ko.y = cvt_f16x2(k0.w * fc0.z + k0.z * fs0.z, k0.z * fc0.z - k0.w * fs0.z);
        ko.z = cvt_f16x2(k1.y * fc1.x + k1.x * fs1.x, k1.x * fc1.x - k1.y * fs1.x);
        ko.w = cvt_f16x2(k1.w * fc1.z + k1.z * fs1.z, k1.z * fc1.z - k1.w * fs1.z);
        vo.x = cvt_f16x2(v0.y, v0.x);
        vo.y = cvt_f16x2(v0.w, v0.z);
        vo.z = cvt_f16x2(v1.y, v1.x);
        vo.w = cvt_f16x2(v1.w, v1.z);

        *(uint4*)&g_qh[((size_t)h * S + s) * D + c8] = qo;
        size_t dst = ((size_t)h * NKV + SPLIT + s) * D + c8;
        *(uint4*)&g_kh[dst] = ko;
        *(uint4*)&g_vh[dst] = vo;
    } else {
        int i8 = idx - ROPE_ITEMS;
        if (i8 >= CONV_ITEMS) return;
        int c8 = (i8 & 7) << 3;
        int h  = (i8 >> 3) & 15;
        int j  = i8 >> 7;
        size_t src = (size_t)(CACHE_OFF + j) * (H * D) + h * D + c8;
        float4 k0 = *(const float4*)&cache_k[src];
        float4 k1 = *(const float4*)&cache_k[src + 4];
        float4 v0 = *(const float4*)&cache_v[src];
        float4 v1 = *(const float4*)&cache_v[src + 4];
        uint4 ko = make_uint4(cvt_f16x2(k0.y, k0.x), cvt_f16x2(k0.w, k0.z),
                              cvt_f16x2(k1.y, k1.x), cvt_f16x2(k1.w, k1.z));
        uint4 vo = make_uint4(cvt_f16x2(v0.y, v0.x), cvt_f16x2(v0.w, v0.z),
                              cvt_f16x2(v1.y, v1.x), cvt_f16x2(v1.w, v1.z));
        size_t dst = ((size_t)h * NKV + j) * D + c8;
        *(uint4*)&g_kh[dst] = ko;
        *(uint4*)&g_vh[dst] = vo;
    }
}

// ---------------------------------------------------------------------------
// Flash attention (structure frozen from round 11): fp16 mma m16n8k16,
// ldmatrix A/B (+.trans V), 4-stage ring cp.async (depth-3), fused per-16-key
// block, ones-column L, f16x2 softmax, async Q prologue.
// grid = (8, 16, 8), block = 128 (4 warps x 32 q-rows), 3 CTAs/SM.
// ---------------------------------------------------------------------------
__device__ __forceinline__ void prefetch_tile(uint32_t kbase, uint32_t vbase,
                                              int tid, int h, int kt) {
    const char* ksrc = (const char*)&g_kh[((size_t)h * NKV + (size_t)kt * BN) * D];
    const char* vsrc = (const char*)&g_vh[((size_t)h * NKV + (size_t)kt * BN) * D];
    #pragma unroll
    for (int g = 0; g < 4; g++) {
        int idx = tid + g * 128;
        int r = idx >> 3, c = idx & 7;
        uint32_t off = (uint32_t)(r * KS + c * 8) * 2;
        cp16(kbase + off, ksrc + (size_t)idx * 16);
        cp16(vbase + off, vsrc + (size_t)idx * 16);
    }
}

__global__ __launch_bounds__(128, 3) void attn_fp16() {
    extern __shared__ __align__(16) __half smem[];

    const int h     = blockIdx.y;
    const int q0    = blockIdx.x * BM;
    const int split = blockIdx.z;
    const int tid   = threadIdx.x;
    const int warp  = tid >> 5;
    const int lane  = tid & 31;
    const int gid   = lane >> 2;
    const int tig   = lane & 3;
    const int kt0   = split * TPT;

    const uint32_t sb = (uint32_t)__cvta_generic_to_shared(smem);
    uint32_t kaddr[4], vaddr[4];
    #pragma unroll
    for (int t = 0; t < 4; t++) {
        kaddr[t] = sb + (uint32_t)(t * STAGE_H) * 2u;
        vaddr[t] = kaddr[t] + (uint32_t)TILE_H * 2u;
    }

    const uint32_t loffB =
        (uint32_t)((((lane >> 4) & 1) * 8 + (lane & 7)) * KS * 2 + ((lane >> 3) & 1) * 16);
    const uint32_t loffA =
        (uint32_t)((lane & 15) * KS * 2 + ((lane >> 4) & 1) * 16);
    const uint32_t loffBV =
        (uint32_t)((((lane >> 3) & 1) * 8 + (lane & 7)) * KS * 2 + ((lane >> 4) & 1) * 16);
    const uint32_t loffLV =
        (uint32_t)((((lane >> 3) & 1) * 8 + (lane & 7)) * KS * 2 + 128);

    // prologue: async Q into stage 0 (halves 0-63 of 128 rows)
    {
        const char* qsrc = (const char*)&g_qh[((size_t)h * S + q0) * D];
        #pragma unroll
        for (int g = 0; g < 8; g++) {
            int idx = tid + g * 128;
            int r = idx >> 3, c = idx & 7;
            cp16(sb + (uint32_t)(r * KS + c * 8) * 2, qsrc + (size_t)idx * 16);
        }
        CP_COMMIT();
    }
    prefetch_tile(kaddr[1], vaddr[1], tid, h, kt0);     CP_COMMIT();
    prefetch_tile(kaddr[2], vaddr[2], tid, h, kt0 + 1); CP_COMMIT();
    prefetch_tile(kaddr[3], vaddr[3], tid, h, kt0 + 2); CP_COMMIT();

    // ones-column (dim 64) / zeros (65-71) in all 4 V areas
    {
        const __half one = __float2half(1.0f), zero = __float2half(0.0f);
        for (int i = tid; i < 4 * 64 * 8; i += 128) {
            int t = i >> 9, rem = i & 511;
            int key = rem >> 3, dd = 64 + (rem & 7);
            smem[t * STAGE_H + TILE_H + key * KS + dd] = (dd == 64) ? one : zero;
        }
    }

    CP_WAIT(3);
    __syncthreads();

    uint32_t qa[2][4][4];
    #pragma unroll
    for (int mt = 0; mt < 2; mt++) {
        uint32_t rowbase = sb + (uint32_t)((warp * 32 + mt * 16) * KS * 2) + loffA;
        #pragma unroll
        for (int kk = 0; kk < 4; kk++)
            ldsm_x4(rowbase + (uint32_t)(kk * 32),
                    qa[mt][kk][0], qa[mt][kk][1], qa[mt][kk][2], qa[mt][kk][3]);
    }

    float o[2][8][4];
    #pragma unroll
    for (int mt = 0; mt < 2; mt++)
        #pragma unroll
        for (int nn = 0; nn < 8; nn++)
            o[mt][nn][0] = o[mt][nn][1] = o[mt][nn][2] = o[mt][nn][3] = 0.f;
    float oL[2][4];
    #pragma unroll
    for (int mt = 0; mt < 2; mt++)
        oL[mt][0] = oL[mt][1] = oL[mt][2] = oL[mt][3] = 0.f;

    for (int j = 0; j < TPT; j++) {
        const int cs = (j + 1) & 3;

        if (j + 2 < TPT)      { CP_WAIT(2); }
        else if (j + 1 < TPT) { CP_WAIT(1); }
        else                  { CP_WAIT(0); }
        __syncthreads();

        if (j + 3 < TPT) {
            prefetch_tile(kaddr[j & 3], vaddr[j & 3], tid, h, kt0 + j + 3);
            CP_COMMIT();
        }

        #pragma unroll
        for (int kb = 0; kb < 4; kb++) {
            float sacc[2][2][4];
            #pragma unroll
            for (int mt = 0; mt < 2; mt++)
                #pragma unroll
                for (int nn = 0; nn < 2; nn++)
                    sacc[mt][nn][0] = sacc[mt][nn][1] = sacc[mt][nn][2] = sacc[mt][nn][3] = 0.f;
            #pragma unroll
            for (int kd = 0; kd < 4; kd++) {
                uint32_t b0, b1, b2, b3;
                ldsm_x4(kaddr[cs] + loffB + (uint32_t)(kb * 16 * KS * 2 + kd * 32),
                        b0, b1, b2, b3);
                mma_f16(sacc[0][0], qa[0][kd], b0, b1);
                mma_f16(sacc[0][1], qa[0][kd], b2, b3);
                mma_f16(sacc[1][0], qa[1][kd], b0, b1);
                mma_f16(sacc[1][1], qa[1][kd], b2, b3);
            }
            uint32_t pa[2][4];
            #pragma unroll
            for (int mt = 0; mt < 2; mt++) {
                pa[mt][0] = ex2_f16x2(cvt_f16x2(sacc[mt][0][1], sacc[mt][0][0]));
                pa[mt][1] = ex2_f16x2(cvt_f16x2(sacc[mt][0][3], sacc[mt][0][2]));
                pa[mt][2] = ex2_f16x2(cvt_f16x2(sacc[mt][1][1], sacc[mt][1][0]));
                pa[mt][3] = ex2_f16x2(cvt_f16x2(sacc[mt][1][3], sacc[mt][1][2]));
            }
            {
                uint32_t bL0, bL1;
                ldsm_x2_t(vaddr[cs] + loffLV + (uint32_t)(kb * 16 * KS * 2), bL0, bL1);
                mma_f16(oL[0], pa[0], bL0, bL1);
                mma_f16(oL[1], pa[1], bL0, bL1);
            }
            #pragma unroll
            for (int nnp = 0; nnp < 4; nnp++) {
                uint32_t b0, b1, b2, b3;
                ldsm_x4_t(vaddr[cs] + loffBV + (uint32_t)(kb * 16 * KS * 2 + nnp * 32),
                          b0, b1, b2, b3);
                mma_f16(o[0][2 * nnp],     pa[0], b0, b1);
                mma_f16(o[0][2 * nnp + 1], pa[0], b2, b3);
                mma_f16(o[1][2 * nnp],     pa[1], b0, b1);
                mma_f16(o[1][2 * nnp + 1], pa[1], b2, b3);
            }
        }
    }

    // epilogue: fp16 partial O via streaming stores (g_po read-once by reduce),
    // fp32 L
    #pragma unroll
    for (int mt = 0; mt < 2; mt++) {
        int r = q0 + warp * 32 + mt * 16 + gid;
        size_t b0 = ((size_t)split * S + r) * (H * D) + h * 64;
        size_t b1 = ((size_t)split * S + r + 8) * (H * D) + h * 64;
        #pragma unroll
        for (int nn = 0; nn < 8; nn++) {
            stg_cs_u32(&g_po[b0 + nn * 8 + 2 * tig], cvt_f16x2(o[mt][nn][1], o[mt][nn][0]));
            stg_cs_u32(&g_po[b1 + nn * 8 + 2 * tig], cvt_f16x2(o[mt][nn][3], o[mt][nn][2]));
        }
        if (tig == 0) {
            g_l[(size_t)split * (S * H) + (size_t)r * H + h]       = oL[mt][0];
            g_l[(size_t)split * (S * H) + (size_t)(r + 8) * H + h] = oL[mt][2];
        }
    }
}

// ---------------------------------------------------------------------------
// Merge splits: 4 outputs per thread (more threads -> latency hiding).
// ---------------------------------------------------------------------------
__global__ __launch_bounds__(256) void reduce_kernel(float* __restrict__ out) {
    int t = blockIdx.x * blockDim.x + threadIdx.x;   // S*H*D/4 threads
    if (t >= S * H * D / 4) return;
    int idx = t * 4;
    int h = (idx >> 6) & 15;
    int s = idx >> 10;
    int mlb = s * H + h;

    float den = 0.f;
    #pragma unroll
    for (int i = 0; i < NSPLIT; i++)
        den += g_l[(size_t)i * (S * H) + mlb];

    float acc0 = 0.f, acc1 = 0.f, acc2 = 0.f, acc3 = 0.f;
    #pragma unroll
    for (int i = 0; i < NSPLIT; i++) {
        uint2 pk = *(const uint2*)&g_po[(size_t)i * (S * H * D) + idx];
        float2 a0 = __half22float2(*(const __half2*)&pk.x);
        float2 a1 = __half22float2(*(const __half2*)&pk.y);
        acc0 += a0.x; acc1 += a0.y; acc2 += a1.x; acc3 += a1.y;
    }
    float r = 1.f / den;
    *(float4*)&out[idx] = make_float4(acc0 * r, acc1 * r, acc2 * r, acc3 * r);
}

// ---------------------------------------------------------------------------
extern "C" void kernel_launch(void* const* d_in, const int* in_sizes, int n_in,
                              void* d_out, int out_size) {
    const float* q  = (const float*)d_in[0];
    const float* k  = (const float*)d_in[1];
    const float* v  = (const float*)d_in[2];
    const float* ck = (const float*)d_in[3];
    const float* cv = (const float*)d_in[4];
    const float* fc = (const float*)d_in[5];
    const float* fs = (const float*)d_in[6];
    float* out = (float*)d_out;
    (void)in_sizes; (void)n_in; (void)out_size;

    int prep_items = ROPE_ITEMS + CONV_ITEMS;
    prep_fused<<<(prep_items + 255) / 256, 256>>>(q, k, v, ck, cv, fc, fs);

    cudaFuncSetAttribute(attn_fp16, cudaFuncAttributeMaxDynamicSharedMemorySize,
                         SM_HALVES * 2);
    dim3 grid(S / BM, H, NSPLIT);
    attn_fp16<<<grid, 128, SM_HALVES * 2>>>();

    reduce_kernel<<<(S * H * D / 4 + 255) / 256, 256>>>(out);
}